// round 6
// baseline (speedup 1.0000x reference)
#include <cuda_runtime.h>
#include <cuda_bf16.h>
#include <math.h>

// ---------------------------------------------------------------------------
// Problem constants
// ---------------------------------------------------------------------------
#define G_NUM  1024
#define P_N    75
#define DEG_E  8
#define N_N    (G_NUM * P_N)
#define E_N    (N_N * DEG_E)
#define EPG    (P_N * DEG_E)          // 600 edges/graph
#define RPG    (EPG * 4)              // 2400 records/graph
#define KS_C   5
#define KK_C   25                     // spline kernels
#define NKEY   (P_N * KK_C)           // 1875 (k,dst) buckets
#define NOFF   (NKEY + 1)
#define YQ     68                     // padded Y row stride (floats, 64 cols + 4)
#define SLAB   608                    // max records per k per graph
#define NTC    320                    // conv threads (10 warps)

// ---------------------------------------------------------------------------
// Device scratch (static — no runtime allocation)
// ---------------------------------------------------------------------------
__device__ float          d_wArr[G_NUM * RPG];     // basis weights, (k,dst)-sorted
__device__ unsigned char  d_sArr[G_NUM * RPG];     // local src per record
__device__ unsigned short d_off2[G_NUM * NOFF];    // CSR offsets over (k*75+dst)
__device__ unsigned short d_deg [G_NUM * P_N];     // in-degree per node
__device__ float d_h1[N_N * 32];
__device__ float d_h2[N_N * 64];
__device__ float d_h3[N_N * 64];

__device__ __forceinline__ float elu_f(float v) { return v > 0.0f ? v : expm1f(v); }

__device__ __forceinline__ unsigned pk2(float a, float b) {
    __nv_bfloat162 t = __floats2bfloat162_rn(a, b);
    return reinterpret_cast<unsigned&>(t);
}
__device__ __forceinline__ float bhi(float v) {
    return __bfloat162float(__float2bfloat16(v));
}

__device__ __forceinline__ void mma_bf16(float c[4], const unsigned a[4],
                                         unsigned b0, unsigned b1) {
    asm volatile(
        "mma.sync.aligned.m16n8k16.row.col.f32.bf16.bf16.f32 "
        "{%0,%1,%2,%3}, {%4,%5,%6,%7}, {%8,%9}, {%0,%1,%2,%3};"
        : "+f"(c[0]), "+f"(c[1]), "+f"(c[2]), "+f"(c[3])
        : "r"(a[0]), "r"(a[1]), "r"(a[2]), "r"(a[3]), "r"(b0), "r"(b1));
}

// ---------------------------------------------------------------------------
// Bucket kernel: spline basis + counting sort of records by (k, dst) + degree
// ---------------------------------------------------------------------------
__global__ __launch_bounds__(256)
void bucket_kernel(const int* __restrict__ edge_index, const float* __restrict__ edge_attr) {
    __shared__ unsigned short skey[RPG];
    __shared__ unsigned char  ssr [RPG];
    __shared__ float          swt [RPG];
    __shared__ int cnt[NKEY];
    __shared__ int part[240];
    __shared__ int dcnt[P_N];

    const int g = blockIdx.x, tid = threadIdx.x;
    for (int t = tid; t < NKEY; t += 256) cnt[t] = 0;
    if (tid < P_N) dcnt[tid] = 0;
    __syncthreads();

    for (int el = tid; el < EPG; el += 256) {
        const int e  = g * EPG + el;
        const float u0 = edge_attr[2 * e], u1 = edge_attr[2 * e + 1];
        const int src = edge_index[e]       - g * P_N;
        const int dst = edge_index[E_N + e] - g * P_N;
        atomicAdd(&dcnt[dst], 1);
        float p0 = u0 * (KS_C - 1), p1 = u1 * (KS_C - 1);
        float l0 = fminf(fmaxf(floorf(p0), 0.0f), (float)(KS_C - 1));
        float l1 = fminf(fmaxf(floorf(p1), 0.0f), (float)(KS_C - 1));
        float f0 = p0 - l0, f1 = p1 - l1;
        int i00 = (int)l0, i01 = min(i00 + 1, KS_C - 1);
        int i10 = (int)l1, i11 = min(i10 + 1, KS_C - 1);
        const float wa[2] = {1.0f - f0, f0};  const int ia[2] = {i00, i01};
        const float wb[2] = {1.0f - f1, f1};  const int ib[2] = {i10, i11};
        #pragma unroll
        for (int a = 0; a < 2; a++)
            #pragma unroll
            for (int b = 0; b < 2; b++) {
                const int slot = el * 4 + a * 2 + b;
                const int k = ia[a] + KS_C * ib[b];
                const int key = k * P_N + dst;          // (k, dst) order
                skey[slot] = (unsigned short)key;
                ssr [slot] = (unsigned char)src;
                swt [slot] = wa[a] * wb[b];
                atomicAdd(&cnt[key], 1);
            }
    }
    __syncthreads();

    if (tid < 235) {
        int s = 0;
        #pragma unroll
        for (int j = 0; j < 8; j++) { int idx = tid * 8 + j; if (idx < NKEY) s += cnt[idx]; }
        part[tid] = s;
    }
    __syncthreads();
    if (tid == 0) {
        int run = 0;
        for (int j = 0; j < 235; j++) { int t = part[j]; part[j] = run; run += t; }
    }
    __syncthreads();
    if (tid < 235) {
        int base = part[tid];
        #pragma unroll
        for (int j = 0; j < 8; j++) {
            int idx = tid * 8 + j;
            if (idx < NKEY) { int c = cnt[idx]; cnt[idx] = base; base += c; }
        }
    }
    __syncthreads();

    for (int t = tid; t < NKEY; t += 256)
        d_off2[g * NOFF + t] = (unsigned short)cnt[t];
    if (tid == 0) d_off2[g * NOFF + NKEY] = (unsigned short)RPG;
    if (tid < P_N) d_deg[g * P_N + tid] = (unsigned short)dcnt[tid];
    __syncthreads();

    for (int slot = tid; slot < RPG; slot += 256) {
        const int key = skey[slot];
        const int p = atomicAdd(&cnt[key], 1);
        d_wArr[g * RPG + p] = swt[slot];
        d_sArr[g * RPG + p] = ssr[slot];
    }
}

// ---------------------------------------------------------------------------
// Conv1 (I=1, O=32): scalar, cheap
// ---------------------------------------------------------------------------
__global__ __launch_bounds__(256)
void conv1_kernel(const float* __restrict__ x, const float* __restrict__ W1,
                  const float* __restrict__ root1, const float* __restrict__ b1,
                  float* __restrict__ out) {
    __shared__ float xs[P_N];
    __shared__ float sdk[NKEY];
    __shared__ float W1s[KK_C * 32];
    __shared__ float r1s[32], b1s[32];
    __shared__ unsigned short off2[NOFF];

    const int g = blockIdx.x, tid = threadIdx.x;
    if (tid < P_N) xs[tid] = x[g * P_N + tid];
    for (int t = tid; t < KK_C * 32; t += 256) W1s[t] = W1[t];
    if (tid < 32) { r1s[tid] = root1[tid]; b1s[tid] = b1[tid]; }
    {
        const unsigned* srcO = (const unsigned*)(d_off2 + g * NOFF);
        unsigned* dstO = (unsigned*)off2;
        for (int t = tid; t < NOFF / 2; t += 256) dstO[t] = srcO[t];
    }
    __syncthreads();

    const float* __restrict__ gw = d_wArr + g * RPG;
    const unsigned char* __restrict__ gs = d_sArr + g * RPG;
    for (int it = tid; it < NKEY; it += 256) {
        int lo = off2[it], hi = off2[it + 1];
        float s = 0.0f;
        for (int r = lo; r < hi; r++) s += gw[r] * xs[gs[r]];
        sdk[it] = s;
    }
    __syncthreads();

    for (int it = tid; it < P_N * 32; it += 256) {
        const int d = it >> 5, o = it & 31;
        float acc = 0.0f;
        #pragma unroll
        for (int k = 0; k < KK_C; k++) acc += sdk[k * P_N + d] * W1s[k * 32 + o];
        const float inv = 1.0f / (float)max((int)d_deg[g * P_N + d], 1);
        out[(g * P_N + d) * 32 + o] = elu_f(acc * inv + xs[d] * r1s[o] + b1s[o]);
    }
}

// ---------------------------------------------------------------------------
// GEMM chunk: Y[80,64] = h(80xI) @ Wmat(Ix64), bf16x3 compensated
//   r0 includes the lane row (gr): rows r0 and r0+8 of the 16-row tile.
// ---------------------------------------------------------------------------
template<int I>
__device__ __forceinline__
void gemm_chunk(const unsigned* __restrict__ hsHi, const unsigned* __restrict__ hsLo,
                const unsigned* __restrict__ wsHi, const unsigned* __restrict__ wsLo,
                float* __restrict__ Ys, int r0, int gr, int cg, int ncol0) {
    constexpr int KST = I / 16;
    constexpr int HP  = I / 2 + 1;
    constexpr int WP  = I / 2 + 1;
    float Ca[4][4], Cb[4][4];
    #pragma unroll
    for (int j = 0; j < 4; j++)
        #pragma unroll
        for (int q = 0; q < 4; q++) { Ca[j][q] = 0.0f; Cb[j][q] = 0.0f; }

    #pragma unroll
    for (int ks = 0; ks < KST; ks++) {
        const int p0 = ks * 8 + cg;
        unsigned aHi[4] = { hsHi[r0 * HP + p0],     hsHi[(r0 + 8) * HP + p0],
                            hsHi[r0 * HP + p0 + 4], hsHi[(r0 + 8) * HP + p0 + 4] };
        unsigned aLo[4] = { hsLo[r0 * HP + p0],     hsLo[(r0 + 8) * HP + p0],
                            hsLo[r0 * HP + p0 + 4], hsLo[(r0 + 8) * HP + p0 + 4] };
        #pragma unroll
        for (int j = 0; j < 4; j++) {
            const int n0 = ncol0 + j * 8;
            const unsigned* bh = wsHi + (n0 + gr) * WP;
            const unsigned* bl = wsLo + (n0 + gr) * WP;
            const unsigned b0h = bh[p0], b1h = bh[p0 + 4];
            const unsigned b0l = bl[p0], b1l = bl[p0 + 4];
            mma_bf16(Ca[j], aHi, b0h, b1h);
            mma_bf16(Cb[j], aLo, b0h, b1h);
            mma_bf16(Cb[j], aHi, b0l, b1l);
        }
    }
    #pragma unroll
    for (int j = 0; j < 4; j++) {
        float* yp = Ys + r0 * YQ + ncol0 + j * 8 + 2 * cg;
        *(float2*)yp            = make_float2(Ca[j][0] + Cb[j][0], Ca[j][1] + Cb[j][1]);
        *(float2*)(yp + 8 * YQ) = make_float2(Ca[j][2] + Cb[j][2], Ca[j][3] + Cb[j][3]);
    }
}

// ---------------------------------------------------------------------------
// Conv (I in {32,64}, O=64): per chunk (one weight matrix):
//   phase A: slab prefetch (gmem->smem) + GEMM Y=h@W_c
//   phase B: gather chunk records + stage W_{c+1}
// ---------------------------------------------------------------------------
template<int I>
__global__ __launch_bounds__(NTC, 3)
void convT_kernel(const float* __restrict__ hin, const float* __restrict__ W,
                  const float* __restrict__ root, const float* __restrict__ bias,
                  float* __restrict__ hout) {
    constexpr int KH = I / 2;
    constexpr int HP = KH + 1;
    constexpr int WP = KH + 1;

    extern __shared__ __align__(16) char smraw[];
    float*          Ys   = (float*)smraw;                 // 80*YQ
    unsigned*       hsHi = (unsigned*)(Ys + 80 * YQ);     // 80*HP
    unsigned*       hsLo = hsHi + 80 * HP;
    unsigned*       wsHi = hsLo + 80 * HP;                // 64*WP
    unsigned*       wsLo = wsHi + 64 * WP;
    float*          slw  = (float*)(wsLo + 64 * WP);      // SLAB
    unsigned short* off2 = (unsigned short*)(slw + SLAB); // NOFF
    unsigned char*  sls  = (unsigned char*)(off2 + NOFF); // SLAB

    const int g = blockIdx.x, tid = threadIdx.x;

    // ---- prologue: h -> bf16 hi/lo, offsets, stage W mat 0
    for (int t = tid; t < P_N * KH; t += NTC) {
        const int r = t / KH, p = t - r * KH;
        float2 v = *(const float2*)(hin + (g * P_N + r) * I + 2 * p);
        float h0 = bhi(v.x), h1 = bhi(v.y);
        hsHi[r * HP + p] = pk2(h0, h1);
        hsLo[r * HP + p] = pk2(v.x - h0, v.y - h1);
    }
    for (int t = tid; t < 5 * KH; t += NTC) {
        const int r = P_N + t / KH, p = t % KH;
        hsHi[r * HP + p] = 0; hsLo[r * HP + p] = 0;
    }
    {
        const unsigned* o4 = (const unsigned*)(d_off2 + g * NOFF);
        unsigned* t4 = (unsigned*)off2;
        for (int t = tid; t < NOFF / 2; t += NTC) t4[t] = o4[t];
    }
    for (int t = tid; t < 64 * KH; t += NTC) {
        const int o = t & 63, ipair = t >> 6;
        float w0 = W[(2 * ipair) * 64 + o], w1 = W[(2 * ipair + 1) * 64 + o];
        float h0 = bhi(w0), h1 = bhi(w1);
        wsHi[o * WP + ipair] = pk2(h0, h1);
        wsLo[o * WP + ipair] = pk2(w0 - h0, w1 - h1);
    }
    __syncthreads();

    // ---- per-thread identity
    const int w = tid >> 5, lane = tid & 31;
    const int gr = lane >> 2, cg = lane & 3;
    const int r0 = (w >> 1) * 16 + gr;         // includes lane row!
    const int ncol0 = (w & 1) * 32;
    const int d = tid >> 2, q = tid & 3;       // gather identity

    const float* __restrict__ gw = d_wArr + g * RPG;
    const unsigned char* __restrict__ gs = d_sArr + g * RPG;

    float agg[16];
    #pragma unroll
    for (int j = 0; j < 16; j++) agg[j] = 0.0f;

    for (int c = 0; c < KK_C; c++) {
        // ---- phase A: slab prefetch + GEMM(c)
        const int base = off2[c * P_N];
        const int nrec = (int)off2[c * P_N + P_N] - base;
        for (int t = tid; t < nrec; t += NTC) {
            slw[t] = gw[base + t];
            sls[t] = gs[base + t];
        }
        gemm_chunk<I>(hsHi, hsLo, wsHi, wsLo, Ys, r0, gr, cg, ncol0);
        __syncthreads();

        // ---- phase B: gather(c) + stage W(c+1)
        if (d < P_N) {
            const int lo = (int)off2[c * P_N + d] - base;
            const int hi = (int)off2[c * P_N + d + 1] - base;
            const float* yq = Ys + q * 16;
            for (int r = lo; r < hi; r++) {
                const float wv = slw[r];
                const float4* yp = (const float4*)(yq + (int)sls[r] * YQ);
                #pragma unroll
                for (int jj = 0; jj < 4; jj++) {
                    float4 v = yp[jj];
                    agg[4 * jj + 0] = fmaf(wv, v.x, agg[4 * jj + 0]);
                    agg[4 * jj + 1] = fmaf(wv, v.y, agg[4 * jj + 1]);
                    agg[4 * jj + 2] = fmaf(wv, v.z, agg[4 * jj + 2]);
                    agg[4 * jj + 3] = fmaf(wv, v.w, agg[4 * jj + 3]);
                }
            }
        }
        {
            const float* Wp = (c + 1 < KK_C) ? (W + (c + 1) * I * 64) : root;
            for (int t = tid; t < 64 * KH; t += NTC) {
                const int o = t & 63, ipair = t >> 6;
                float w0 = Wp[(2 * ipair) * 64 + o], w1 = Wp[(2 * ipair + 1) * 64 + o];
                float h0 = bhi(w0), h1 = bhi(w1);
                wsHi[o * WP + ipair] = pk2(h0, h1);
                wsLo[o * WP + ipair] = pk2(w0 - h0, w1 - h1);
            }
        }
        __syncthreads();
    }

    // ---- final GEMM: Y_root = h @ root
    gemm_chunk<I>(hsHi, hsLo, wsHi, wsLo, Ys, r0, gr, cg, ncol0);
    __syncthreads();

    // ---- epilogue: mean-scale + root + bias + ELU
    if (d < P_N) {
        const float inv = 1.0f / (float)max((int)d_deg[g * P_N + d], 1);
        const float4* rt = (const float4*)(Ys + d * YQ + q * 16);
        float* op = hout + (g * P_N + d) * 64 + q * 16;
        #pragma unroll
        for (int jj = 0; jj < 4; jj++) {
            float4 r4 = rt[jj];
            float4 o4;
            o4.x = elu_f(agg[4 * jj + 0] * inv + r4.x + bias[q * 16 + 4 * jj + 0]);
            o4.y = elu_f(agg[4 * jj + 1] * inv + r4.y + bias[q * 16 + 4 * jj + 1]);
            o4.z = elu_f(agg[4 * jj + 2] * inv + r4.z + bias[q * 16 + 4 * jj + 2]);
            o4.w = elu_f(agg[4 * jj + 3] * inv + r4.w + bias[q * 16 + 4 * jj + 3]);
            *(float4*)(op + 4 * jj) = o4;
        }
    }
}

// ---------------------------------------------------------------------------
// Head: voxel max-pool + fc1/ELU + fc2 + log_softmax
// ---------------------------------------------------------------------------
__global__ __launch_bounds__(256)
void head_kernel(const float* __restrict__ h3, const float* __restrict__ pos,
                 const float* __restrict__ fc1w, const float* __restrict__ fc1b,
                 const float* __restrict__ fc2w, const float* __restrict__ fc2b,
                 float* __restrict__ out) {
    __shared__ float hs[P_N * 64];
    __shared__ int   vox[P_N];
    __shared__ float gx[256];
    __shared__ float f1[128];
    __shared__ float lg[10];

    const int g = blockIdx.x, tid = threadIdx.x;
    for (int t = tid; t < P_N * 64; t += 256) hs[t] = h3[g * P_N * 64 + t];
    if (tid < P_N) {
        const float p0 = pos[(g * P_N + tid) * 2 + 0];
        const float p1 = pos[(g * P_N + tid) * 2 + 1];
        const int v0 = min(max((int)(p0 / 14.0f), 0), 1);
        const int v1 = min(max((int)(p1 / 14.0f), 0), 1);
        vox[tid] = v0 + 2 * v1;
    }
    __syncthreads();
    {
        const int v = tid >> 6, c = tid & 63;
        float m = -3.402823466e38f; bool found = false;
        for (int r = 0; r < P_N; r++)
            if (vox[r] == v) { m = fmaxf(m, hs[r * 64 + c]); found = true; }
        gx[v * 64 + c] = found ? m : 0.0f;
    }
    __syncthreads();
    if (tid < 128) {
        float a = fc1b[tid];
        #pragma unroll 8
        for (int i = 0; i < 256; i++) a = fmaf(gx[i], fc1w[i * 128 + tid], a);
        f1[tid] = elu_f(a);
    }
    __syncthreads();
    if (tid < 10) {
        float a = fc2b[tid];
        #pragma unroll 8
        for (int i = 0; i < 128; i++) a = fmaf(f1[i], fc2w[i * 10 + tid], a);
        lg[tid] = a;
    }
    __syncthreads();
    if (tid == 0) {
        float m = lg[0];
        for (int o = 1; o < 10; o++) m = fmaxf(m, lg[o]);
        float s = 0.0f;
        for (int o = 0; o < 10; o++) s += expf(lg[o] - m);
        const float lse = m + logf(s);
        for (int o = 0; o < 10; o++) out[g * 10 + o] = lg[o] - lse;
    }
}

// ---------------------------------------------------------------------------
// Launch
// ---------------------------------------------------------------------------
static int conv_smem_bytes(int I) {
    const int KH = I / 2, HP = KH + 1, WP = KH + 1;
    const int u32s = 80 * YQ + 2 * 80 * HP + 2 * 64 * WP + SLAB;
    return u32s * 4 + NOFF * 2 + SLAB + 16;
}

extern "C" void kernel_launch(void* const* d_in, const int* in_sizes, int n_in,
                              void* d_out, int out_size) {
    const float* x     = (const float*)d_in[0];
    const int*   eidx  = (const int*)  d_in[1];
    const float* eattr = (const float*)d_in[2];
    const float* pos   = (const float*)d_in[4];
    const float* W1    = (const float*)d_in[5];
    const float* root1 = (const float*)d_in[6];
    const float* b1    = (const float*)d_in[7];
    const float* W2    = (const float*)d_in[8];
    const float* root2 = (const float*)d_in[9];
    const float* b2    = (const float*)d_in[10];
    const float* W3    = (const float*)d_in[11];
    const float* root3 = (const float*)d_in[12];
    const float* b3    = (const float*)d_in[13];
    const float* fc1w  = (const float*)d_in[14];
    const float* fc1b  = (const float*)d_in[15];
    const float* fc2w  = (const float*)d_in[16];
    const float* fc2b  = (const float*)d_in[17];
    float* out = (float*)d_out;

    void *h1p = nullptr, *h2p = nullptr, *h3p = nullptr;
    cudaGetSymbolAddress(&h1p, d_h1);
    cudaGetSymbolAddress(&h2p, d_h2);
    cudaGetSymbolAddress(&h3p, d_h3);

    const int s2 = conv_smem_bytes(32);
    const int s3 = conv_smem_bytes(64);
    cudaFuncSetAttribute(convT_kernel<32>, cudaFuncAttributeMaxDynamicSharedMemorySize, s2);
    cudaFuncSetAttribute(convT_kernel<64>, cudaFuncAttributeMaxDynamicSharedMemorySize, s3);

    bucket_kernel<<<G_NUM, 256>>>(eidx, eattr);
    conv1_kernel<<<G_NUM, 256>>>(x, W1, root1, b1, (float*)h1p);
    convT_kernel<32><<<G_NUM, NTC, s2>>>((const float*)h1p, W2, root2, b2, (float*)h2p);
    convT_kernel<64><<<G_NUM, NTC, s3>>>((const float*)h2p, W3, root3, b3, (float*)h3p);
    head_kernel<<<G_NUM, 256>>>((const float*)h3p, pos, fc1w, fc1b, fc2w, fc2b, out);
}

// round 7
// speedup vs baseline: 1.5148x; 1.5148x over previous
#include <cuda_runtime.h>
#include <cuda_bf16.h>
#include <math.h>

// ---------------------------------------------------------------------------
// Problem constants
// ---------------------------------------------------------------------------
#define G_NUM  1024
#define P_N    75
#define DEG_E  8
#define N_N    (G_NUM * P_N)
#define E_N    (N_N * DEG_E)
#define EPG    (P_N * DEG_E)          // 600 edges/graph
#define RPG    (EPG * 4)              // 2400 records/graph
#define KS_C   5
#define KK_C   25                     // spline kernels
#define NKEY   (P_N * KK_C)           // 1875 (k,dst) buckets
#define NOFF   (NKEY + 1)
#define YP     132                    // padded Y row stride (floats) — 132 % 8 == 4
#define SLAB2  1216                   // max records per 2-k chunk (hard cap 1200)
#define NTC    320                    // conv threads (10 warps)

// ---------------------------------------------------------------------------
// Device scratch (static — no runtime allocation)
// ---------------------------------------------------------------------------
__device__ float          d_wArr[G_NUM * RPG];     // basis weights, (k,dst)-sorted
__device__ unsigned char  d_sArr[G_NUM * RPG];     // local src per record
__device__ unsigned short d_off2[G_NUM * NOFF];    // CSR offsets over (k*75+dst)
__device__ unsigned short d_deg [G_NUM * P_N];     // in-degree per node
__device__ float d_h1[N_N * 32];
__device__ float d_h2[N_N * 64];
__device__ float d_h3[N_N * 64];

__device__ __forceinline__ float elu_f(float v) { return v > 0.0f ? v : expm1f(v); }

__device__ __forceinline__ unsigned pk2(float a, float b) {
    __nv_bfloat162 t = __floats2bfloat162_rn(a, b);
    return reinterpret_cast<unsigned&>(t);
}
__device__ __forceinline__ float bhi(float v) {
    return __bfloat162float(__float2bfloat16(v));
}

__device__ __forceinline__ void mma_bf16(float c[4], const unsigned a[4],
                                         unsigned b0, unsigned b1) {
    asm volatile(
        "mma.sync.aligned.m16n8k16.row.col.f32.bf16.bf16.f32 "
        "{%0,%1,%2,%3}, {%4,%5,%6,%7}, {%8,%9}, {%0,%1,%2,%3};"
        : "+f"(c[0]), "+f"(c[1]), "+f"(c[2]), "+f"(c[3])
        : "r"(a[0]), "r"(a[1]), "r"(a[2]), "r"(a[3]), "r"(b0), "r"(b1));
}

// ---------------------------------------------------------------------------
// Bucket kernel: spline basis + counting sort of records by (k, dst) + degree
// ---------------------------------------------------------------------------
__global__ __launch_bounds__(256)
void bucket_kernel(const int* __restrict__ edge_index, const float* __restrict__ edge_attr) {
    __shared__ unsigned short skey[RPG];
    __shared__ unsigned char  ssr [RPG];
    __shared__ float          swt [RPG];
    __shared__ int cnt[NKEY];
    __shared__ int part[240];
    __shared__ int dcnt[P_N];

    const int g = blockIdx.x, tid = threadIdx.x;
    for (int t = tid; t < NKEY; t += 256) cnt[t] = 0;
    if (tid < P_N) dcnt[tid] = 0;
    __syncthreads();

    for (int el = tid; el < EPG; el += 256) {
        const int e  = g * EPG + el;
        const float u0 = edge_attr[2 * e], u1 = edge_attr[2 * e + 1];
        const int src = edge_index[e]       - g * P_N;
        const int dst = edge_index[E_N + e] - g * P_N;
        atomicAdd(&dcnt[dst], 1);
        float p0 = u0 * (KS_C - 1), p1 = u1 * (KS_C - 1);
        float l0 = fminf(fmaxf(floorf(p0), 0.0f), (float)(KS_C - 1));
        float l1 = fminf(fmaxf(floorf(p1), 0.0f), (float)(KS_C - 1));
        float f0 = p0 - l0, f1 = p1 - l1;
        int i00 = (int)l0, i01 = min(i00 + 1, KS_C - 1);
        int i10 = (int)l1, i11 = min(i10 + 1, KS_C - 1);
        const float wa[2] = {1.0f - f0, f0};  const int ia[2] = {i00, i01};
        const float wb[2] = {1.0f - f1, f1};  const int ib[2] = {i10, i11};
        #pragma unroll
        for (int a = 0; a < 2; a++)
            #pragma unroll
            for (int b = 0; b < 2; b++) {
                const int slot = el * 4 + a * 2 + b;
                const int k = ia[a] + KS_C * ib[b];
                const int key = k * P_N + dst;          // (k, dst) order
                skey[slot] = (unsigned short)key;
                ssr [slot] = (unsigned char)src;
                swt [slot] = wa[a] * wb[b];
                atomicAdd(&cnt[key], 1);
            }
    }
    __syncthreads();

    if (tid < 235) {
        int s = 0;
        #pragma unroll
        for (int j = 0; j < 8; j++) { int idx = tid * 8 + j; if (idx < NKEY) s += cnt[idx]; }
        part[tid] = s;
    }
    __syncthreads();
    if (tid == 0) {
        int run = 0;
        for (int j = 0; j < 235; j++) { int t = part[j]; part[j] = run; run += t; }
    }
    __syncthreads();
    if (tid < 235) {
        int base = part[tid];
        #pragma unroll
        for (int j = 0; j < 8; j++) {
            int idx = tid * 8 + j;
            if (idx < NKEY) { int c = cnt[idx]; cnt[idx] = base; base += c; }
        }
    }
    __syncthreads();

    for (int t = tid; t < NKEY; t += 256)
        d_off2[g * NOFF + t] = (unsigned short)cnt[t];
    if (tid == 0) d_off2[g * NOFF + NKEY] = (unsigned short)RPG;
    if (tid < P_N) d_deg[g * P_N + tid] = (unsigned short)dcnt[tid];
    __syncthreads();

    for (int slot = tid; slot < RPG; slot += 256) {
        const int key = skey[slot];
        const int p = atomicAdd(&cnt[key], 1);
        d_wArr[g * RPG + p] = swt[slot];
        d_sArr[g * RPG + p] = ssr[slot];
    }
}

// ---------------------------------------------------------------------------
// Conv1 (I=1, O=32): scalar, cheap
// ---------------------------------------------------------------------------
__global__ __launch_bounds__(256)
void conv1_kernel(const float* __restrict__ x, const float* __restrict__ W1,
                  const float* __restrict__ root1, const float* __restrict__ b1,
                  float* __restrict__ out) {
    __shared__ float xs[P_N];
    __shared__ float sdk[NKEY];
    __shared__ float W1s[KK_C * 32];
    __shared__ float r1s[32], b1s[32];
    __shared__ unsigned short off2[NOFF];

    const int g = blockIdx.x, tid = threadIdx.x;
    if (tid < P_N) xs[tid] = x[g * P_N + tid];
    for (int t = tid; t < KK_C * 32; t += 256) W1s[t] = W1[t];
    if (tid < 32) { r1s[tid] = root1[tid]; b1s[tid] = b1[tid]; }
    {
        const unsigned* srcO = (const unsigned*)(d_off2 + g * NOFF);
        unsigned* dstO = (unsigned*)off2;
        for (int t = tid; t < NOFF / 2; t += 256) dstO[t] = srcO[t];
    }
    __syncthreads();

    const float* __restrict__ gw = d_wArr + g * RPG;
    const unsigned char* __restrict__ gs = d_sArr + g * RPG;
    for (int it = tid; it < NKEY; it += 256) {
        int lo = off2[it], hi = off2[it + 1];
        float s = 0.0f;
        for (int r = lo; r < hi; r++) s += gw[r] * xs[gs[r]];
        sdk[it] = s;
    }
    __syncthreads();

    for (int it = tid; it < P_N * 32; it += 256) {
        const int d = it >> 5, o = it & 31;
        float acc = 0.0f;
        #pragma unroll
        for (int k = 0; k < KK_C; k++) acc += sdk[k * P_N + d] * W1s[k * 32 + o];
        const float inv = 1.0f / (float)max((int)d_deg[g * P_N + d], 1);
        out[(g * P_N + d) * 32 + o] = elu_f(acc * inv + xs[d] * r1s[o] + b1s[o]);
    }
}

// ---------------------------------------------------------------------------
// Conv (I in {32,64}, O=64): chunk = 2 weight matrices (13 chunks, last = W24|root).
//   phase A: slab prefetch (records of this chunk, gmem->smem) + GEMM Y=h@[Wa|Wb]
//   phase B: gather chunk records + stage next W pair
//   A-fragments persistent in registers; all smem strides ≡ 4 (mod 8) -> no conflicts.
// ---------------------------------------------------------------------------
template<int I>
__global__ __launch_bounds__(NTC, 2)
void convT_kernel(const float* __restrict__ hin, const float* __restrict__ W,
                  const float* __restrict__ root, const float* __restrict__ bias,
                  float* __restrict__ hout) {
    constexpr int KH  = I / 2;       // bf16 pairs along K
    constexpr int HP  = KH + 4;      // padded h row stride (u32): 36 / 20 -> conflict-free
    constexpr int WP  = KH + 4;      // padded W per-col stride (u32)
    constexpr int KST = I / 16;      // mma k-steps

    extern __shared__ __align__(16) char smraw[];
    float*          Ys   = (float*)smraw;                  // 80*YP
    unsigned*       hsHi = (unsigned*)(Ys + 80 * YP);      // 80*HP
    unsigned*       hsLo = hsHi + 80 * HP;
    unsigned*       wsHi = hsLo + 80 * HP;                 // 2*64*WP (2 mats)
    unsigned*       wsLo = wsHi + 2 * 64 * WP;
    float*          slw  = (float*)(wsLo + 2 * 64 * WP);   // SLAB2
    unsigned short* off2 = (unsigned short*)(slw + SLAB2); // NOFF
    unsigned char*  sls  = (unsigned char*)(off2 + NOFF);  // SLAB2

    const int g = blockIdx.x, tid = threadIdx.x;

    // ---- prologue: h -> bf16 hi/lo, offsets, stage W mats 0,1
    for (int t = tid; t < P_N * KH; t += NTC) {
        const int r = t / KH, p = t - r * KH;
        float2 v = *(const float2*)(hin + (g * P_N + r) * I + 2 * p);
        float h0 = bhi(v.x), h1 = bhi(v.y);
        hsHi[r * HP + p] = pk2(h0, h1);
        hsLo[r * HP + p] = pk2(v.x - h0, v.y - h1);
    }
    for (int t = tid; t < 5 * KH; t += NTC) {
        const int r = P_N + t / KH, p = t % KH;
        hsHi[r * HP + p] = 0; hsLo[r * HP + p] = 0;
    }
    {
        const unsigned* o4 = (const unsigned*)(d_off2 + g * NOFF);
        unsigned* t4 = (unsigned*)off2;
        for (int t = tid; t < NOFF / 2; t += NTC) t4[t] = o4[t];
    }
    for (int t = tid; t < 2 * 64 * KH; t += NTC) {
        const int mm = t / (64 * KH), rem = t - mm * 64 * KH;
        const int o = rem & 63, ipair = rem >> 6;
        const float* Wp = W + mm * I * 64;                 // mats 0,1
        float w0 = Wp[(2 * ipair) * 64 + o], w1 = Wp[(2 * ipair + 1) * 64 + o];
        float h0 = bhi(w0), h1 = bhi(w1);
        wsHi[(mm * 64 + o) * WP + ipair] = pk2(h0, h1);
        wsLo[(mm * 64 + o) * WP + ipair] = pk2(w0 - h0, w1 - h1);
    }
    __syncthreads();

    // ---- per-thread identity
    const int w = tid >> 5, lane = tid & 31;
    const int gr = lane >> 2, cg = lane & 3;
    const int mt = w >> 1;                 // 5 M-tiles, 2 warps each
    const int matw = w & 1;                // warp's matrix slot within chunk
    const int r0 = mt * 16 + gr;
    const int d = tid >> 2, q = tid & 3;   // gather identity

    // A fragments: fixed for whole kernel (conflict-free loads: HP % 8 == 4)
    unsigned aHi[KST][4], aLo[KST][4];
    #pragma unroll
    for (int ks = 0; ks < KST; ks++) {
        const int p0 = ks * 8 + cg;
        aHi[ks][0] = hsHi[r0 * HP + p0];       aHi[ks][1] = hsHi[(r0 + 8) * HP + p0];
        aHi[ks][2] = hsHi[r0 * HP + p0 + 4];   aHi[ks][3] = hsHi[(r0 + 8) * HP + p0 + 4];
        aLo[ks][0] = hsLo[r0 * HP + p0];       aLo[ks][1] = hsLo[(r0 + 8) * HP + p0];
        aLo[ks][2] = hsLo[r0 * HP + p0 + 4];   aLo[ks][3] = hsLo[(r0 + 8) * HP + p0 + 4];
    }

    const float* __restrict__ gw = d_wArr + g * RPG;
    const unsigned char* __restrict__ gs = d_sArr + g * RPG;

    float agg[16];
    #pragma unroll
    for (int j = 0; j < 16; j++) agg[j] = 0.0f;

    for (int c = 0; c < 13; c++) {
        // ---- phase A: slab prefetch + GEMM(c): Y[80,128] = h @ [mat 2c | mat 2c+1]
        const int base = off2[(2 * c) * P_N];
        const int endi = min((2 * c + 2) * P_N, NKEY);
        const int nrec = (int)off2[endi] - base;
        for (int t = tid; t < nrec; t += NTC) {
            slw[t] = gw[base + t];
            sls[t] = gs[base + t];
        }
        #pragma unroll
        for (int j = 0; j < 8; j++) {
            const int n0 = j * 8;
            const unsigned* bh = wsHi + (matw * 64 + n0 + gr) * WP;
            const unsigned* bl = wsLo + (matw * 64 + n0 + gr) * WP;
            float Ca[4] = {0, 0, 0, 0}, Cb[4] = {0, 0, 0, 0};
            #pragma unroll
            for (int ks = 0; ks < KST; ks++) {
                const int p0 = ks * 8 + cg;
                const unsigned b0h = bh[p0], b1h = bh[p0 + 4];
                const unsigned b0l = bl[p0], b1l = bl[p0 + 4];
                mma_bf16(Ca, aHi[ks], b0h, b1h);
                mma_bf16(Cb, aLo[ks], b0h, b1h);
                mma_bf16(Cb, aHi[ks], b0l, b1l);
            }
            float* yp = Ys + r0 * YP + matw * 64 + n0 + 2 * cg;
            *(float2*)yp            = make_float2(Ca[0] + Cb[0], Ca[1] + Cb[1]);
            *(float2*)(yp + 8 * YP) = make_float2(Ca[2] + Cb[2], Ca[3] + Cb[3]);
        }
        __syncthreads();   // Y + slab ready; Ws free

        // ---- phase B: gather(c) + stage W(c+1)
        if (d < P_N) {
            #pragma unroll
            for (int mm = 0; mm < 2; mm++) {
                const int gk = 2 * c + mm;
                if (gk < KK_C) {
                    const int lo = (int)off2[gk * P_N + d] - base;
                    const int hi = (int)off2[gk * P_N + d + 1] - base;
                    const float* yq = Ys + mm * 64 + q * 16;
                    for (int r = lo; r < hi; r++) {
                        const float wv = slw[r];
                        const float4* yp = (const float4*)(yq + (int)sls[r] * YP);
                        #pragma unroll
                        for (int jj = 0; jj < 4; jj++) {
                            float4 v = yp[jj];
                            agg[4 * jj + 0] = fmaf(wv, v.x, agg[4 * jj + 0]);
                            agg[4 * jj + 1] = fmaf(wv, v.y, agg[4 * jj + 1]);
                            agg[4 * jj + 2] = fmaf(wv, v.z, agg[4 * jj + 2]);
                            agg[4 * jj + 3] = fmaf(wv, v.w, agg[4 * jj + 3]);
                        }
                    }
                }
            }
        }
        if (c < 12) {
            for (int t = tid; t < 2 * 64 * KH; t += NTC) {
                const int mm = t / (64 * KH), rem = t - mm * 64 * KH;
                const int o = rem & 63, ipair = rem >> 6;
                const int gm = 2 * (c + 1) + mm;
                const float* Wp = (gm < KK_C) ? (W + gm * I * 64) : root;
                float w0 = Wp[(2 * ipair) * 64 + o], w1 = Wp[(2 * ipair + 1) * 64 + o];
                float h0 = bhi(w0), h1 = bhi(w1);
                wsHi[(mm * 64 + o) * WP + ipair] = pk2(h0, h1);
                wsLo[(mm * 64 + o) * WP + ipair] = pk2(w0 - h0, w1 - h1);
            }
        }
        __syncthreads();   // Ws(c+1) ready; gather done -> Y reusable
    }

    // ---- epilogue: mean-scale + root (chunk 12, mat slot 1) + bias + ELU
    if (d < P_N) {
        const float inv = 1.0f / (float)max((int)d_deg[g * P_N + d], 1);
        const float4* rt = (const float4*)(Ys + d * YP + 64 + q * 16);
        float* op = hout + (g * P_N + d) * 64 + q * 16;
        #pragma unroll
        for (int jj = 0; jj < 4; jj++) {
            float4 r4 = rt[jj];
            float4 o4;
            o4.x = elu_f(agg[4 * jj + 0] * inv + r4.x + bias[q * 16 + 4 * jj + 0]);
            o4.y = elu_f(agg[4 * jj + 1] * inv + r4.y + bias[q * 16 + 4 * jj + 1]);
            o4.z = elu_f(agg[4 * jj + 2] * inv + r4.z + bias[q * 16 + 4 * jj + 2]);
            o4.w = elu_f(agg[4 * jj + 3] * inv + r4.w + bias[q * 16 + 4 * jj + 3]);
            *(float4*)(op + 4 * jj) = o4;
        }
    }
}

// ---------------------------------------------------------------------------
// Head: voxel max-pool + fc1/ELU + fc2 + log_softmax
// ---------------------------------------------------------------------------
__global__ __launch_bounds__(256)
void head_kernel(const float* __restrict__ h3, const float* __restrict__ pos,
                 const float* __restrict__ fc1w, const float* __restrict__ fc1b,
                 const float* __restrict__ fc2w, const float* __restrict__ fc2b,
                 float* __restrict__ out) {
    __shared__ float hs[P_N * 64];
    __shared__ int   vox[P_N];
    __shared__ float gx[256];
    __shared__ float f1[128];
    __shared__ float lg[10];

    const int g = blockIdx.x, tid = threadIdx.x;
    for (int t = tid; t < P_N * 64; t += 256) hs[t] = h3[g * P_N * 64 + t];
    if (tid < P_N) {
        const float p0 = pos[(g * P_N + tid) * 2 + 0];
        const float p1 = pos[(g * P_N + tid) * 2 + 1];
        const int v0 = min(max((int)(p0 / 14.0f), 0), 1);
        const int v1 = min(max((int)(p1 / 14.0f), 0), 1);
        vox[tid] = v0 + 2 * v1;
    }
    __syncthreads();
    {
        const int v = tid >> 6, c = tid & 63;
        float m = -3.402823466e38f; bool found = false;
        for (int r = 0; r < P_N; r++)
            if (vox[r] == v) { m = fmaxf(m, hs[r * 64 + c]); found = true; }
        gx[v * 64 + c] = found ? m : 0.0f;
    }
    __syncthreads();
    if (tid < 128) {
        float a = fc1b[tid];
        #pragma unroll 8
        for (int i = 0; i < 256; i++) a = fmaf(gx[i], fc1w[i * 128 + tid], a);
        f1[tid] = elu_f(a);
    }
    __syncthreads();
    if (tid < 10) {
        float a = fc2b[tid];
        #pragma unroll 8
        for (int i = 0; i < 128; i++) a = fmaf(f1[i], fc2w[i * 10 + tid], a);
        lg[tid] = a;
    }
    __syncthreads();
    if (tid == 0) {
        float m = lg[0];
        for (int o = 1; o < 10; o++) m = fmaxf(m, lg[o]);
        float s = 0.0f;
        for (int o = 0; o < 10; o++) s += expf(lg[o] - m);
        const float lse = m + logf(s);
        for (int o = 0; o < 10; o++) out[g * 10 + o] = lg[o] - lse;
    }
}

// ---------------------------------------------------------------------------
// Launch
// ---------------------------------------------------------------------------
static int conv_smem_bytes(int I) {
    const int KH = I / 2, HP = KH + 4, WP = KH + 4;
    const int u32s = 80 * YP + 2 * 80 * HP + 4 * 64 * WP + SLAB2;
    return u32s * 4 + NOFF * 2 + SLAB2 + 16;
}

extern "C" void kernel_launch(void* const* d_in, const int* in_sizes, int n_in,
                              void* d_out, int out_size) {
    const float* x     = (const float*)d_in[0];
    const int*   eidx  = (const int*)  d_in[1];
    const float* eattr = (const float*)d_in[2];
    const float* pos   = (const float*)d_in[4];
    const float* W1    = (const float*)d_in[5];
    const float* root1 = (const float*)d_in[6];
    const float* b1    = (const float*)d_in[7];
    const float* W2    = (const float*)d_in[8];
    const float* root2 = (const float*)d_in[9];
    const float* b2    = (const float*)d_in[10];
    const float* W3    = (const float*)d_in[11];
    const float* root3 = (const float*)d_in[12];
    const float* b3    = (const float*)d_in[13];
    const float* fc1w  = (const float*)d_in[14];
    const float* fc1b  = (const float*)d_in[15];
    const float* fc2w  = (const float*)d_in[16];
    const float* fc2b  = (const float*)d_in[17];
    float* out = (float*)d_out;

    void *h1p = nullptr, *h2p = nullptr, *h3p = nullptr;
    cudaGetSymbolAddress(&h1p, d_h1);
    cudaGetSymbolAddress(&h2p, d_h2);
    cudaGetSymbolAddress(&h3p, d_h3);

    const int s2 = conv_smem_bytes(32);
    const int s3 = conv_smem_bytes(64);
    cudaFuncSetAttribute(convT_kernel<32>, cudaFuncAttributeMaxDynamicSharedMemorySize, s2);
    cudaFuncSetAttribute(convT_kernel<64>, cudaFuncAttributeMaxDynamicSharedMemorySize, s3);

    bucket_kernel<<<G_NUM, 256>>>(eidx, eattr);
    conv1_kernel<<<G_NUM, 256>>>(x, W1, root1, b1, (float*)h1p);
    convT_kernel<32><<<G_NUM, NTC, s2>>>((const float*)h1p, W2, root2, b2, (float*)h2p);
    convT_kernel<64><<<G_NUM, NTC, s3>>>((const float*)h2p, W3, root3, b3, (float*)h3p);
    head_kernel<<<G_NUM, 256>>>((const float*)h3p, pos, fc1w, fc1b, fc2w, fc2b, out);
}

// round 8
// speedup vs baseline: 1.7831x; 1.1772x over previous
#include <cuda_runtime.h>
#include <cuda_bf16.h>
#include <math.h>

// ---------------------------------------------------------------------------
// Problem constants
// ---------------------------------------------------------------------------
#define G_NUM  1024
#define P_N    75
#define DEG_E  8
#define N_N    (G_NUM * P_N)
#define E_N    (N_N * DEG_E)
#define EPG    (P_N * DEG_E)          // 600 edges/graph
#define RPG    (EPG * 4)              // 2400 records/graph
#define KS_C   5
#define KK_C   25                     // spline kernels
#define NKEY   (P_N * KK_C)           // 1875 (k,dst) buckets
#define NOFF   (NKEY + 1)
#define YP     132                    // padded Y row stride (floats) — 132 % 8 == 4
#define SLAB2  1216                   // max records per 2-k chunk (hard cap 1200)
#define NTC    320                    // conv threads (10 warps)
#define WP32   20                     // padded W col stride (u32), I=32 — 20 % 8 == 4
#define WP64   36                     // padded W col stride (u32), I=64 — 36 % 8 == 4

// ---------------------------------------------------------------------------
// Device scratch (static — no runtime allocation)
// ---------------------------------------------------------------------------
__device__ float          d_wArr[G_NUM * RPG];     // basis weights, (k,dst)-sorted
__device__ unsigned char  d_sArr[G_NUM * RPG];     // local src per record
__device__ unsigned short d_off2[G_NUM * NOFF];    // CSR offsets over (k*75+dst)
__device__ unsigned short d_deg [G_NUM * P_N];     // in-degree per node
__device__ float d_h1[N_N * 32];
__device__ float d_h2[N_N * 64];
__device__ float d_h3[N_N * 64];
// Pre-split / pre-transposed weights: [mat][o][ipair], mats 0..24 = W_k, 25 = root
__device__ unsigned d_W32hi[26 * 64 * WP32];
__device__ unsigned d_W32lo[26 * 64 * WP32];
__device__ unsigned d_W64hi[26 * 64 * WP64];
__device__ unsigned d_W64lo[26 * 64 * WP64];

__device__ __forceinline__ float elu_f(float v) { return v > 0.0f ? v : expm1f(v); }

__device__ __forceinline__ unsigned pk2(float a, float b) {
    __nv_bfloat162 t = __floats2bfloat162_rn(a, b);
    return reinterpret_cast<unsigned&>(t);
}
__device__ __forceinline__ float bhi(float v) {
    return __bfloat162float(__float2bfloat16(v));
}

__device__ __forceinline__ void mma_bf16(float c[4], const unsigned a[4],
                                         unsigned b0, unsigned b1) {
    asm volatile(
        "mma.sync.aligned.m16n8k16.row.col.f32.bf16.bf16.f32 "
        "{%0,%1,%2,%3}, {%4,%5,%6,%7}, {%8,%9}, {%0,%1,%2,%3};"
        : "+f"(c[0]), "+f"(c[1]), "+f"(c[2]), "+f"(c[3])
        : "r"(a[0]), "r"(a[1]), "r"(a[2]), "r"(a[3]), "r"(b0), "r"(b1));
}

// ---------------------------------------------------------------------------
// Prep kernel: split W (+root) into bf16 hi/lo, transposed [mat][o][ipair]
// One block per mat (26 per layer).
// ---------------------------------------------------------------------------
__global__ __launch_bounds__(256)
void prep_kernel(const float* __restrict__ W, const float* __restrict__ root,
                 unsigned* __restrict__ oHi, unsigned* __restrict__ oLo,
                 int I, int WPv) {
    const int mat = blockIdx.x;
    const float* Wp = (mat < KK_C) ? (W + mat * I * 64) : root;
    const int KHv = I / 2;
    for (int t = threadIdx.x; t < 64 * KHv; t += 256) {
        const int o = t & 63, ipair = t >> 6;
        float w0 = Wp[(2 * ipair) * 64 + o], w1 = Wp[(2 * ipair + 1) * 64 + o];
        float h0 = bhi(w0), h1 = bhi(w1);
        oHi[(mat * 64 + o) * WPv + ipair] = pk2(h0, h1);
        oLo[(mat * 64 + o) * WPv + ipair] = pk2(w0 - h0, w1 - h1);
    }
    // zero the padding tail so uint4 copies stage defined data
    for (int t = threadIdx.x; t < 64 * (WPv - KHv); t += 256) {
        const int o = t % 64, p = KHv + t / 64;
        oHi[(mat * 64 + o) * WPv + p] = 0;
        oLo[(mat * 64 + o) * WPv + p] = 0;
    }
}

// ---------------------------------------------------------------------------
// Bucket kernel: spline basis + counting sort of records by (k, dst) + degree
// ---------------------------------------------------------------------------
__global__ __launch_bounds__(256)
void bucket_kernel(const int* __restrict__ edge_index, const float* __restrict__ edge_attr) {
    __shared__ unsigned short skey[RPG];
    __shared__ unsigned char  ssr [RPG];
    __shared__ float          swt [RPG];
    __shared__ int cnt[NKEY];
    __shared__ int part[240];
    __shared__ int dcnt[P_N];

    const int g = blockIdx.x, tid = threadIdx.x;
    for (int t = tid; t < NKEY; t += 256) cnt[t] = 0;
    if (tid < P_N) dcnt[tid] = 0;
    __syncthreads();

    for (int el = tid; el < EPG; el += 256) {
        const int e  = g * EPG + el;
        const float u0 = edge_attr[2 * e], u1 = edge_attr[2 * e + 1];
        const int src = edge_index[e]       - g * P_N;
        const int dst = edge_index[E_N + e] - g * P_N;
        atomicAdd(&dcnt[dst], 1);
        float p0 = u0 * (KS_C - 1), p1 = u1 * (KS_C - 1);
        float l0 = fminf(fmaxf(floorf(p0), 0.0f), (float)(KS_C - 1));
        float l1 = fminf(fmaxf(floorf(p1), 0.0f), (float)(KS_C - 1));
        float f0 = p0 - l0, f1 = p1 - l1;
        int i00 = (int)l0, i01 = min(i00 + 1, KS_C - 1);
        int i10 = (int)l1, i11 = min(i10 + 1, KS_C - 1);
        const float wa[2] = {1.0f - f0, f0};  const int ia[2] = {i00, i01};
        const float wb[2] = {1.0f - f1, f1};  const int ib[2] = {i10, i11};
        #pragma unroll
        for (int a = 0; a < 2; a++)
            #pragma unroll
            for (int b = 0; b < 2; b++) {
                const int slot = el * 4 + a * 2 + b;
                const int k = ia[a] + KS_C * ib[b];
                const int key = k * P_N + dst;          // (k, dst) order
                skey[slot] = (unsigned short)key;
                ssr [slot] = (unsigned char)src;
                swt [slot] = wa[a] * wb[b];
                atomicAdd(&cnt[key], 1);
            }
    }
    __syncthreads();

    if (tid < 235) {
        int s = 0;
        #pragma unroll
        for (int j = 0; j < 8; j++) { int idx = tid * 8 + j; if (idx < NKEY) s += cnt[idx]; }
        part[tid] = s;
    }
    __syncthreads();
    if (tid == 0) {
        int run = 0;
        for (int j = 0; j < 235; j++) { int t = part[j]; part[j] = run; run += t; }
    }
    __syncthreads();
    if (tid < 235) {
        int base = part[tid];
        #pragma unroll
        for (int j = 0; j < 8; j++) {
            int idx = tid * 8 + j;
            if (idx < NKEY) { int c = cnt[idx]; cnt[idx] = base; base += c; }
        }
    }
    __syncthreads();

    for (int t = tid; t < NKEY; t += 256)
        d_off2[g * NOFF + t] = (unsigned short)cnt[t];
    if (tid == 0) d_off2[g * NOFF + NKEY] = (unsigned short)RPG;
    if (tid < P_N) d_deg[g * P_N + tid] = (unsigned short)dcnt[tid];
    __syncthreads();

    for (int slot = tid; slot < RPG; slot += 256) {
        const int key = skey[slot];
        const int p = atomicAdd(&cnt[key], 1);
        d_wArr[g * RPG + p] = swt[slot];
        d_sArr[g * RPG + p] = ssr[slot];
    }
}

// ---------------------------------------------------------------------------
// Conv1 (I=1, O=32): scalar, cheap
// ---------------------------------------------------------------------------
__global__ __launch_bounds__(256)
void conv1_kernel(const float* __restrict__ x, const float* __restrict__ W1,
                  const float* __restrict__ root1, const float* __restrict__ b1,
                  float* __restrict__ out) {
    __shared__ float xs[P_N];
    __shared__ float sdk[NKEY];
    __shared__ float W1s[KK_C * 32];
    __shared__ float r1s[32], b1s[32];
    __shared__ unsigned short off2[NOFF];

    const int g = blockIdx.x, tid = threadIdx.x;
    if (tid < P_N) xs[tid] = x[g * P_N + tid];
    for (int t = tid; t < KK_C * 32; t += 256) W1s[t] = W1[t];
    if (tid < 32) { r1s[tid] = root1[tid]; b1s[tid] = b1[tid]; }
    {
        const unsigned* srcO = (const unsigned*)(d_off2 + g * NOFF);
        unsigned* dstO = (unsigned*)off2;
        for (int t = tid; t < NOFF / 2; t += 256) dstO[t] = srcO[t];
    }
    __syncthreads();

    const float* __restrict__ gw = d_wArr + g * RPG;
    const unsigned char* __restrict__ gs = d_sArr + g * RPG;
    for (int it = tid; it < NKEY; it += 256) {
        int lo = off2[it], hi = off2[it + 1];
        float s = 0.0f;
        for (int r = lo; r < hi; r++) s += gw[r] * xs[gs[r]];
        sdk[it] = s;
    }
    __syncthreads();

    for (int it = tid; it < P_N * 32; it += 256) {
        const int d = it >> 5, o = it & 31;
        float acc = 0.0f;
        #pragma unroll
        for (int k = 0; k < KK_C; k++) acc += sdk[k * P_N + d] * W1s[k * 32 + o];
        const float inv = 1.0f / (float)max((int)d_deg[g * P_N + d], 1);
        out[(g * P_N + d) * 32 + o] = elu_f(acc * inv + xs[d] * r1s[o] + b1s[o]);
    }
}

// ---------------------------------------------------------------------------
// Conv (I in {32,64}, O=64): chunk = 2 weight matrices (13 chunks, last = W24|root).
//   phase A: slab prefetch (records, gmem->smem) + GEMM Y=h@[Wa|Wb]
//   phase B: gather chunk records + uint4-copy next W pair (pre-split in gmem)
// ---------------------------------------------------------------------------
template<int I>
__global__ __launch_bounds__(NTC, 2)
void convT_kernel(const float* __restrict__ hin,
                  const unsigned* __restrict__ gWhi, const unsigned* __restrict__ gWlo,
                  const float* __restrict__ bias, float* __restrict__ hout) {
    constexpr int KH  = I / 2;       // bf16 pairs along K
    constexpr int HP  = KH + 4;      // padded h row stride (u32) — conflict-free
    constexpr int WP  = KH + 4;      // padded W per-col stride (u32)
    constexpr int KST = I / 16;      // mma k-steps
    constexpr int WCH = 2 * 64 * WP; // u32 per 2-mat chunk

    extern __shared__ __align__(16) char smraw[];
    float*          Ys   = (float*)smraw;                  // 80*YP
    unsigned*       hsHi = (unsigned*)(Ys + 80 * YP);      // 80*HP
    unsigned*       hsLo = hsHi + 80 * HP;
    unsigned*       wsHi = hsLo + 80 * HP;                 // WCH
    unsigned*       wsLo = wsHi + WCH;
    float*          slw  = (float*)(wsLo + WCH);           // SLAB2
    unsigned short* off2 = (unsigned short*)(slw + SLAB2); // NOFF
    unsigned char*  sls  = (unsigned char*)(off2 + NOFF);  // SLAB2

    const int g = blockIdx.x, tid = threadIdx.x;

    // ---- prologue: h -> bf16 hi/lo, offsets, uint4-copy W chunk 0
    for (int t = tid; t < P_N * KH; t += NTC) {
        const int r = t / KH, p = t - r * KH;
        float2 v = *(const float2*)(hin + (g * P_N + r) * I + 2 * p);
        float h0 = bhi(v.x), h1 = bhi(v.y);
        hsHi[r * HP + p] = pk2(h0, h1);
        hsLo[r * HP + p] = pk2(v.x - h0, v.y - h1);
    }
    for (int t = tid; t < 5 * KH; t += NTC) {
        const int r = P_N + t / KH, p = t % KH;
        hsHi[r * HP + p] = 0; hsLo[r * HP + p] = 0;
    }
    {
        const unsigned* o4 = (const unsigned*)(d_off2 + g * NOFF);
        unsigned* t4 = (unsigned*)off2;
        for (int t = tid; t < NOFF / 2; t += NTC) t4[t] = o4[t];
    }
    {
        const uint4* sH = (const uint4*)gWhi;
        const uint4* sL = (const uint4*)gWlo;
        uint4* dH = (uint4*)wsHi;
        uint4* dL = (uint4*)wsLo;
        for (int t = tid; t < WCH / 4; t += NTC) { dH[t] = sH[t]; dL[t] = sL[t]; }
    }
    __syncthreads();

    // ---- per-thread identity
    const int w = tid >> 5, lane = tid & 31;
    const int gr = lane >> 2, cg = lane & 3;
    const int mt = w >> 1;                 // 5 M-tiles, 2 warps each
    const int matw = w & 1;                // warp's matrix slot within chunk
    const int r0 = mt * 16 + gr;
    const int d = tid >> 2, q = tid & 3;   // gather identity

    // A fragments: fixed for whole kernel (conflict-free: HP % 8 == 4)
    unsigned aHi[KST][4], aLo[KST][4];
    #pragma unroll
    for (int ks = 0; ks < KST; ks++) {
        const int p0 = ks * 8 + cg;
        aHi[ks][0] = hsHi[r0 * HP + p0];       aHi[ks][1] = hsHi[(r0 + 8) * HP + p0];
        aHi[ks][2] = hsHi[r0 * HP + p0 + 4];   aHi[ks][3] = hsHi[(r0 + 8) * HP + p0 + 4];
        aLo[ks][0] = hsLo[r0 * HP + p0];       aLo[ks][1] = hsLo[(r0 + 8) * HP + p0];
        aLo[ks][2] = hsLo[r0 * HP + p0 + 4];   aLo[ks][3] = hsLo[(r0 + 8) * HP + p0 + 4];
    }

    const float* __restrict__ gw = d_wArr + g * RPG;
    const unsigned char* __restrict__ gs = d_sArr + g * RPG;

    float agg[16];
    #pragma unroll
    for (int j = 0; j < 16; j++) agg[j] = 0.0f;

    for (int c = 0; c < 13; c++) {
        // ---- phase A: slab prefetch + GEMM(c): Y[80,128] = h @ [mat 2c | mat 2c+1]
        const int base = off2[(2 * c) * P_N];
        const int endi = min((2 * c + 2) * P_N, NKEY);
        const int nrec = (int)off2[endi] - base;
        for (int t = tid; t < nrec; t += NTC) {
            slw[t] = gw[base + t];
            sls[t] = gs[base + t];
        }
        #pragma unroll
        for (int j = 0; j < 8; j++) {
            const int n0 = j * 8;
            const unsigned* bh = wsHi + (matw * 64 + n0 + gr) * WP;
            const unsigned* bl = wsLo + (matw * 64 + n0 + gr) * WP;
            float Ca[4] = {0, 0, 0, 0}, Cb[4] = {0, 0, 0, 0};
            #pragma unroll
            for (int ks = 0; ks < KST; ks++) {
                const int p0 = ks * 8 + cg;
                const unsigned b0h = bh[p0], b1h = bh[p0 + 4];
                const unsigned b0l = bl[p0], b1l = bl[p0 + 4];
                mma_bf16(Ca, aHi[ks], b0h, b1h);
                mma_bf16(Cb, aLo[ks], b0h, b1h);
                mma_bf16(Cb, aHi[ks], b0l, b1l);
            }
            float* yp = Ys + r0 * YP + matw * 64 + n0 + 2 * cg;
            *(float2*)yp            = make_float2(Ca[0] + Cb[0], Ca[1] + Cb[1]);
            *(float2*)(yp + 8 * YP) = make_float2(Ca[2] + Cb[2], Ca[3] + Cb[3]);
        }
        __syncthreads();   // Y + slab ready; Ws free

        // ---- phase B: gather(c) + uint4-copy W(c+1)
        if (d < P_N) {
            #pragma unroll
            for (int mm = 0; mm < 2; mm++) {
                const int gk = 2 * c + mm;
                if (gk < KK_C) {
                    const int lo = (int)off2[gk * P_N + d] - base;
                    const int hi = (int)off2[gk * P_N + d + 1] - base;
                    const float* yq = Ys + mm * 64 + q * 16;
                    for (int r = lo; r < hi; r++) {
                        const float wv = slw[r];
                        const float4* yp = (const float4*)(yq + (int)sls[r] * YP);
                        #pragma unroll
                        for (int jj = 0; jj < 4; jj++) {
                            float4 v = yp[jj];
                            agg[4 * jj + 0] = fmaf(wv, v.x, agg[4 * jj + 0]);
                            agg[4 * jj + 1] = fmaf(wv, v.y, agg[4 * jj + 1]);
                            agg[4 * jj + 2] = fmaf(wv, v.z, agg[4 * jj + 2]);
                            agg[4 * jj + 3] = fmaf(wv, v.w, agg[4 * jj + 3]);
                        }
                    }
                }
            }
        }
        if (c < 12) {
            const uint4* sH = (const uint4*)(gWhi + (2 * (c + 1)) * (64 * WP));
            const uint4* sL = (const uint4*)(gWlo + (2 * (c + 1)) * (64 * WP));
            uint4* dH = (uint4*)wsHi;
            uint4* dL = (uint4*)wsLo;
            for (int t = tid; t < WCH / 4; t += NTC) { dH[t] = sH[t]; dL[t] = sL[t]; }
        }
        __syncthreads();   // Ws(c+1) ready; gather done -> Y reusable
    }

    // ---- epilogue: mean-scale + root (chunk 12, mat slot 1) + bias + ELU
    if (d < P_N) {
        const float inv = 1.0f / (float)max((int)d_deg[g * P_N + d], 1);
        const float4* rt = (const float4*)(Ys + d * YP + 64 + q * 16);
        float* op = hout + (g * P_N + d) * 64 + q * 16;
        #pragma unroll
        for (int jj = 0; jj < 4; jj++) {
            float4 r4 = rt[jj];
            float4 o4;
            o4.x = elu_f(agg[4 * jj + 0] * inv + r4.x + bias[q * 16 + 4 * jj + 0]);
            o4.y = elu_f(agg[4 * jj + 1] * inv + r4.y + bias[q * 16 + 4 * jj + 1]);
            o4.z = elu_f(agg[4 * jj + 2] * inv + r4.z + bias[q * 16 + 4 * jj + 2]);
            o4.w = elu_f(agg[4 * jj + 3] * inv + r4.w + bias[q * 16 + 4 * jj + 3]);
            *(float4*)(op + 4 * jj) = o4;
        }
    }
}

// ---------------------------------------------------------------------------
// Head: voxel max-pool + fc1/ELU + fc2 + log_softmax
// ---------------------------------------------------------------------------
__global__ __launch_bounds__(256)
void head_kernel(const float* __restrict__ h3, const float* __restrict__ pos,
                 const float* __restrict__ fc1w, const float* __restrict__ fc1b,
                 const float* __restrict__ fc2w, const float* __restrict__ fc2b,
                 float* __restrict__ out) {
    __shared__ float hs[P_N * 64];
    __shared__ int   vox[P_N];
    __shared__ float gx[256];
    __shared__ float f1[128];
    __shared__ float lg[10];

    const int g = blockIdx.x, tid = threadIdx.x;
    for (int t = tid; t < P_N * 64; t += 256) hs[t] = h3[g * P_N * 64 + t];
    if (tid < P_N) {
        const float p0 = pos[(g * P_N + tid) * 2 + 0];
        const float p1 = pos[(g * P_N + tid) * 2 + 1];
        const int v0 = min(max((int)(p0 / 14.0f), 0), 1);
        const int v1 = min(max((int)(p1 / 14.0f), 0), 1);
        vox[tid] = v0 + 2 * v1;
    }
    __syncthreads();
    {
        const int v = tid >> 6, c = tid & 63;
        float m = -3.402823466e38f; bool found = false;
        for (int r = 0; r < P_N; r++)
            if (vox[r] == v) { m = fmaxf(m, hs[r * 64 + c]); found = true; }
        gx[v * 64 + c] = found ? m : 0.0f;
    }
    __syncthreads();
    if (tid < 128) {
        float a = fc1b[tid];
        #pragma unroll 8
        for (int i = 0; i < 256; i++) a = fmaf(gx[i], fc1w[i * 128 + tid], a);
        f1[tid] = elu_f(a);
    }
    __syncthreads();
    if (tid < 10) {
        float a = fc2b[tid];
        #pragma unroll 8
        for (int i = 0; i < 128; i++) a = fmaf(f1[i], fc2w[i * 10 + tid], a);
        lg[tid] = a;
    }
    __syncthreads();
    if (tid == 0) {
        float m = lg[0];
        for (int o = 1; o < 10; o++) m = fmaxf(m, lg[o]);
        float s = 0.0f;
        for (int o = 0; o < 10; o++) s += expf(lg[o] - m);
        const float lse = m + logf(s);
        for (int o = 0; o < 10; o++) out[g * 10 + o] = lg[o] - lse;
    }
}

// ---------------------------------------------------------------------------
// Launch
// ---------------------------------------------------------------------------
static int conv_smem_bytes(int I) {
    const int KH = I / 2, HP = KH + 4, WP = KH + 4;
    const int u32s = 80 * YP + 2 * 80 * HP + 4 * 64 * WP + SLAB2;
    return u32s * 4 + NOFF * 2 + SLAB2 + 16;
}

extern "C" void kernel_launch(void* const* d_in, const int* in_sizes, int n_in,
                              void* d_out, int out_size) {
    const float* x     = (const float*)d_in[0];
    const int*   eidx  = (const int*)  d_in[1];
    const float* eattr = (const float*)d_in[2];
    const float* pos   = (const float*)d_in[4];
    const float* W1    = (const float*)d_in[5];
    const float* root1 = (const float*)d_in[6];
    const float* b1    = (const float*)d_in[7];
    const float* W2    = (const float*)d_in[8];
    const float* root2 = (const float*)d_in[9];
    const float* b2    = (const float*)d_in[10];
    const float* W3    = (const float*)d_in[11];
    const float* root3 = (const float*)d_in[12];
    const float* b3    = (const float*)d_in[13];
    const float* fc1w  = (const float*)d_in[14];
    const float* fc1b  = (const float*)d_in[15];
    const float* fc2w  = (const float*)d_in[16];
    const float* fc2b  = (const float*)d_in[17];
    float* out = (float*)d_out;

    void *h1p = nullptr, *h2p = nullptr, *h3p = nullptr;
    void *w32h = nullptr, *w32l = nullptr, *w64h = nullptr, *w64l = nullptr;
    cudaGetSymbolAddress(&h1p, d_h1);
    cudaGetSymbolAddress(&h2p, d_h2);
    cudaGetSymbolAddress(&h3p, d_h3);
    cudaGetSymbolAddress(&w32h, d_W32hi);
    cudaGetSymbolAddress(&w32l, d_W32lo);
    cudaGetSymbolAddress(&w64h, d_W64hi);
    cudaGetSymbolAddress(&w64l, d_W64lo);

    const int s2 = conv_smem_bytes(32);
    const int s3 = conv_smem_bytes(64);
    cudaFuncSetAttribute(convT_kernel<32>, cudaFuncAttributeMaxDynamicSharedMemorySize, s2);
    cudaFuncSetAttribute(convT_kernel<64>, cudaFuncAttributeMaxDynamicSharedMemorySize, s3);

    prep_kernel<<<26, 256>>>(W2, root2, (unsigned*)w32h, (unsigned*)w32l, 32, WP32);
    prep_kernel<<<26, 256>>>(W3, root3, (unsigned*)w64h, (unsigned*)w64l, 64, WP64);
    bucket_kernel<<<G_NUM, 256>>>(eidx, eattr);
    conv1_kernel<<<G_NUM, 256>>>(x, W1, root1, b1, (float*)h1p);
    convT_kernel<32><<<G_NUM, NTC, s2>>>((const float*)h1p,
                                         (const unsigned*)w32h, (const unsigned*)w32l,
                                         b2, (float*)h2p);
    convT_kernel<64><<<G_NUM, NTC, s3>>>((const float*)h2p,
                                         (const unsigned*)w64h, (const unsigned*)w64l,
                                         b3, (float*)h3p);
    head_kernel<<<G_NUM, 256>>>((const float*)h3p, pos, fc1w, fc1b, fc2w, fc2b, out);
}

// round 9
// speedup vs baseline: 1.8104x; 1.0153x over previous
#include <cuda_runtime.h>
#include <cuda_bf16.h>
#include <math.h>

// ---------------------------------------------------------------------------
// Problem constants
// ---------------------------------------------------------------------------
#define G_NUM  1024
#define P_N    75
#define DEG_E  8
#define N_N    (G_NUM * P_N)
#define E_N    (N_N * DEG_E)
#define EPG    (P_N * DEG_E)          // 600 edges/graph
#define RPG    (EPG * 4)              // 2400 records/graph
#define KS_C   5
#define KK_C   25
#define NKEY   (P_N * KK_C)           // 1875 (k,dst) buckets
#define NOFF   (NKEY + 1)
#define YP     132                    // Y row stride (floats), 132 % 8 == 4
#define HQ     68                     // hcur row stride (floats), 68 % 8 == 4
#define SLAB2  1216
#define NTC    320
#define WP32   20
#define WP64   36

// ---- smem layout (byte offsets) -------------------------------------------
#define SM_OFF2  0                    // ushort[NOFF]            3752
#define SM_DEG   3760                 // int[P_N]                 300
#define SM_HCUR  4064                 // float[80*HQ]           21760
#define SM_Y     25824                // float[80*YP]           42240
#define SM_W     68064                // u32[2*2*64*WP64]       36864
#define SM_C     104928               // slab / W1 / head        6080
#define SM_TOTAL 111104

// bucket-phase aliases inside the Y region (42240 B available)
#define BK_SWT   (SM_Y + 0)           // float[RPG]   9600
#define BK_CNT   (SM_Y + 9600)        // int[NKEY]    7500
#define BK_SDK   (SM_Y + 17100)       // float[NKEY]  7500
#define BK_KEY   (SM_Y + 24600)       // u16[RPG]     4800
#define BK_SSR   (SM_Y + 29400)       // u8[RPG]      2400
#define BK_PART  (SM_Y + 31800)       // int[240]      960
#define BK_XS    (SM_Y + 32760)       // float[80]     320

// ---------------------------------------------------------------------------
// Device scratch
// ---------------------------------------------------------------------------
__device__ float          d_wArr[G_NUM * RPG];
__device__ unsigned char  d_sArr[G_NUM * RPG];
__device__ unsigned d_W32hi[26 * 64 * WP32];
__device__ unsigned d_W32lo[26 * 64 * WP32];
__device__ unsigned d_W64hi[26 * 64 * WP64];
__device__ unsigned d_W64lo[26 * 64 * WP64];

__device__ __forceinline__ float elu_f(float v) { return v > 0.0f ? v : expm1f(v); }

__device__ __forceinline__ unsigned pk2(float a, float b) {
    __nv_bfloat162 t = __floats2bfloat162_rn(a, b);
    return reinterpret_cast<unsigned&>(t);
}
__device__ __forceinline__ float bhi(float v) {
    return __bfloat162float(__float2bfloat16(v));
}

__device__ __forceinline__ void mma_bf16(float c[4], const unsigned a[4],
                                         unsigned b0, unsigned b1) {
    asm volatile(
        "mma.sync.aligned.m16n8k16.row.col.f32.bf16.bf16.f32 "
        "{%0,%1,%2,%3}, {%4,%5,%6,%7}, {%8,%9}, {%0,%1,%2,%3};"
        : "+f"(c[0]), "+f"(c[1]), "+f"(c[2]), "+f"(c[3])
        : "r"(a[0]), "r"(a[1]), "r"(a[2]), "r"(a[3]), "r"(b0), "r"(b1));
}

// ---------------------------------------------------------------------------
// Prep: split W (+root) into bf16 hi/lo, transposed [mat][o][ipair]
// ---------------------------------------------------------------------------
__global__ __launch_bounds__(256)
void prep_kernel(const float* __restrict__ W, const float* __restrict__ root,
                 unsigned* __restrict__ oHi, unsigned* __restrict__ oLo,
                 int I, int WPv) {
    const int mat = blockIdx.x;
    const float* Wp = (mat < KK_C) ? (W + mat * I * 64) : root;
    const int KHv = I / 2;
    for (int t = threadIdx.x; t < 64 * KHv; t += 256) {
        const int o = t & 63, ipair = t >> 6;
        float w0 = Wp[(2 * ipair) * 64 + o], w1 = Wp[(2 * ipair + 1) * 64 + o];
        float h0 = bhi(w0), h1 = bhi(w1);
        oHi[(mat * 64 + o) * WPv + ipair] = pk2(h0, h1);
        oLo[(mat * 64 + o) * WPv + ipair] = pk2(w0 - h0, w1 - h1);
    }
    for (int t = threadIdx.x; t < 64 * (WPv - KHv); t += 256) {
        const int o = t % 64, p = KHv + t / 64;
        oHi[(mat * 64 + o) * WPv + p] = 0;
        oLo[(mat * 64 + o) * WPv + p] = 0;
    }
}

// ---------------------------------------------------------------------------
// Conv phase (I in {32,64}): identical inner loop to R8 convT_kernel, but
// h input/output live in smem hcur; off2/deg in smem.
// ---------------------------------------------------------------------------
template<int I>
__device__ __forceinline__
void conv_phase(char* sm, const unsigned* __restrict__ gWhi,
                const unsigned* __restrict__ gWlo, const float* __restrict__ bias,
                const float* __restrict__ gw, const unsigned char* __restrict__ gs,
                int tid) {
    constexpr int KH  = I / 2;
    constexpr int KST = I / 16;
    constexpr int WP  = KH + 4;
    constexpr int WCH = 2 * 64 * WP;

    unsigned short* off2 = (unsigned short*)(sm + SM_OFF2);
    int*            degS = (int*)(sm + SM_DEG);
    float*          hcur = (float*)(sm + SM_HCUR);
    float*          Ys   = (float*)(sm + SM_Y);
    unsigned*       wsHi = (unsigned*)(sm + SM_W);
    unsigned*       wsLo = wsHi + WCH;
    float*          slw  = (float*)(sm + SM_C);
    unsigned char*  sls  = (unsigned char*)(sm + SM_C + 4864);

    __syncthreads();   // hcur ready; Y/W/slab regions free

    // stage W chunk 0
    {
        const uint4* sH = (const uint4*)gWhi;
        const uint4* sL = (const uint4*)gWlo;
        uint4* dH = (uint4*)wsHi;
        uint4* dL = (uint4*)wsLo;
        for (int t = tid; t < WCH / 4; t += NTC) { dH[t] = sH[t]; dL[t] = sL[t]; }
    }

    const int w = tid >> 5, lane = tid & 31;
    const int gr = lane >> 2, cg = lane & 3;
    const int mt = w >> 1, matw = w & 1;
    const int r0 = mt * 16 + gr;
    const int d = tid >> 2, q = tid & 3;

    // A fragments straight from fp32 hcur
    unsigned aHi[KST][4], aLo[KST][4];
    #pragma unroll
    for (int ks = 0; ks < KST; ks++) {
        const int p0 = ks * 8 + cg;
        float2 v00 = *(const float2*)(hcur + r0 * HQ + 2 * p0);
        float2 v10 = *(const float2*)(hcur + (r0 + 8) * HQ + 2 * p0);
        float2 v01 = *(const float2*)(hcur + r0 * HQ + 2 * p0 + 8);
        float2 v11 = *(const float2*)(hcur + (r0 + 8) * HQ + 2 * p0 + 8);
        float a, b;
        a = bhi(v00.x); b = bhi(v00.y);
        aHi[ks][0] = pk2(a, b); aLo[ks][0] = pk2(v00.x - a, v00.y - b);
        a = bhi(v10.x); b = bhi(v10.y);
        aHi[ks][1] = pk2(a, b); aLo[ks][1] = pk2(v10.x - a, v10.y - b);
        a = bhi(v01.x); b = bhi(v01.y);
        aHi[ks][2] = pk2(a, b); aLo[ks][2] = pk2(v01.x - a, v01.y - b);
        a = bhi(v11.x); b = bhi(v11.y);
        aHi[ks][3] = pk2(a, b); aLo[ks][3] = pk2(v11.x - a, v11.y - b);
    }
    __syncthreads();   // W0 staged

    float agg[16];
    #pragma unroll
    for (int j = 0; j < 16; j++) agg[j] = 0.0f;

    for (int c = 0; c < 13; c++) {
        // phase A: slab prefetch + GEMM(c)
        const int base = off2[(2 * c) * P_N];
        const int endi = min((2 * c + 2) * P_N, NKEY);
        const int nrec = (int)off2[endi] - base;
        for (int t = tid; t < nrec; t += NTC) {
            slw[t] = gw[base + t];
            sls[t] = gs[base + t];
        }
        #pragma unroll
        for (int j = 0; j < 8; j++) {
            const int n0 = j * 8;
            const unsigned* bh = wsHi + (matw * 64 + n0 + gr) * WP;
            const unsigned* bl = wsLo + (matw * 64 + n0 + gr) * WP;
            float Ca[4] = {0, 0, 0, 0}, Cb[4] = {0, 0, 0, 0};
            #pragma unroll
            for (int ks = 0; ks < KST; ks++) {
                const int p0 = ks * 8 + cg;
                const unsigned b0h = bh[p0], b1h = bh[p0 + 4];
                const unsigned b0l = bl[p0], b1l = bl[p0 + 4];
                mma_bf16(Ca, aHi[ks], b0h, b1h);
                mma_bf16(Cb, aLo[ks], b0h, b1h);
                mma_bf16(Cb, aHi[ks], b0l, b1l);
            }
            float* yp = Ys + r0 * YP + matw * 64 + n0 + 2 * cg;
            *(float2*)yp            = make_float2(Ca[0] + Cb[0], Ca[1] + Cb[1]);
            *(float2*)(yp + 8 * YP) = make_float2(Ca[2] + Cb[2], Ca[3] + Cb[3]);
        }
        __syncthreads();

        // phase B: gather(c) + stage W(c+1)
        if (d < P_N) {
            #pragma unroll
            for (int mm = 0; mm < 2; mm++) {
                const int gk = 2 * c + mm;
                if (gk < KK_C) {
                    const int lo = (int)off2[gk * P_N + d] - base;
                    const int hi = (int)off2[gk * P_N + d + 1] - base;
                    const float* yq = Ys + mm * 64 + q * 16;
                    for (int r = lo; r < hi; r++) {
                        const float wv = slw[r];
                        const float4* yp = (const float4*)(yq + (int)sls[r] * YP);
                        #pragma unroll
                        for (int jj = 0; jj < 4; jj++) {
                            float4 v = yp[jj];
                            agg[4 * jj + 0] = fmaf(wv, v.x, agg[4 * jj + 0]);
                            agg[4 * jj + 1] = fmaf(wv, v.y, agg[4 * jj + 1]);
                            agg[4 * jj + 2] = fmaf(wv, v.z, agg[4 * jj + 2]);
                            agg[4 * jj + 3] = fmaf(wv, v.w, agg[4 * jj + 3]);
                        }
                    }
                }
            }
        }
        if (c < 12) {
            const uint4* sH = (const uint4*)(gWhi + (2 * (c + 1)) * (64 * WP));
            const uint4* sL = (const uint4*)(gWlo + (2 * (c + 1)) * (64 * WP));
            uint4* dH = (uint4*)wsHi;
            uint4* dL = (uint4*)wsLo;
            for (int t = tid; t < WCH / 4; t += NTC) { dH[t] = sH[t]; dL[t] = sL[t]; }
        }
        __syncthreads();
    }

    // epilogue: mean-scale + root (chunk 12, mat slot 1) + bias + ELU -> hcur
    if (d < P_N) {
        const float inv = 1.0f / (float)max(degS[d], 1);
        const float4* rt = (const float4*)(Ys + d * YP + 64 + q * 16);
        float* op = hcur + d * HQ + q * 16;
        #pragma unroll
        for (int jj = 0; jj < 4; jj++) {
            float4 r4 = rt[jj];
            float4 o4;
            o4.x = elu_f(agg[4 * jj + 0] * inv + r4.x + bias[q * 16 + 4 * jj + 0]);
            o4.y = elu_f(agg[4 * jj + 1] * inv + r4.y + bias[q * 16 + 4 * jj + 1]);
            o4.z = elu_f(agg[4 * jj + 2] * inv + r4.z + bias[q * 16 + 4 * jj + 2]);
            o4.w = elu_f(agg[4 * jj + 3] * inv + r4.w + bias[q * 16 + 4 * jj + 3]);
            *(float4*)(op + 4 * jj) = o4;
        }
    }
    __syncthreads();
}

// ---------------------------------------------------------------------------
// Mega kernel: one CTA = one graph, end to end.
// ---------------------------------------------------------------------------
__global__ __launch_bounds__(NTC, 2)
void mega_kernel(const float* __restrict__ x, const int* __restrict__ eidx,
                 const float* __restrict__ eattr, const float* __restrict__ pos,
                 const float* __restrict__ W1, const float* __restrict__ root1,
                 const float* __restrict__ b1,
                 const unsigned* __restrict__ W32hi, const unsigned* __restrict__ W32lo,
                 const float* __restrict__ b2,
                 const unsigned* __restrict__ W64hi, const unsigned* __restrict__ W64lo,
                 const float* __restrict__ b3,
                 const float* __restrict__ fc1w, const float* __restrict__ fc1b,
                 const float* __restrict__ fc2w, const float* __restrict__ fc2b,
                 float* __restrict__ out) {
    extern __shared__ __align__(16) char sm[];
    const int g = blockIdx.x, tid = threadIdx.x;

    unsigned short* off2 = (unsigned short*)(sm + SM_OFF2);
    int*            degS = (int*)(sm + SM_DEG);
    float*          hcur = (float*)(sm + SM_HCUR);
    float*          swt  = (float*)(sm + BK_SWT);
    int*            cnt  = (int*)(sm + BK_CNT);
    float*          sdk  = (float*)(sm + BK_SDK);
    unsigned short* skey = (unsigned short*)(sm + BK_KEY);
    unsigned char*  ssr  = (unsigned char*)(sm + BK_SSR);
    int*            part = (int*)(sm + BK_PART);
    float*          xs   = (float*)(sm + BK_XS);
    float*          W1s  = (float*)(sm + SM_C);          // 800 f
    float*          r1s  = (float*)(sm + SM_C + 3200);   // 32 f
    float*          b1s  = (float*)(sm + SM_C + 3328);   // 32 f

    // ---- init
    for (int t = tid; t < NKEY; t += NTC) { cnt[t] = 0; sdk[t] = 0.0f; }
    if (tid < P_N) { degS[tid] = 0; xs[tid] = x[g * P_N + tid]; }
    for (int t = tid; t < 5 * HQ; t += NTC) hcur[P_N * HQ + t] = 0.0f;  // pad rows
    for (int t = tid; t < KK_C * 32; t += NTC) W1s[t] = W1[t];
    if (tid < 32) { r1s[tid] = root1[tid]; b1s[tid] = b1[tid]; }
    __syncthreads();

    // ---- bucket: basis + records + counts + sdk (conv1 partial sums)
    for (int el = tid; el < EPG; el += NTC) {
        const int e  = g * EPG + el;
        const float u0 = eattr[2 * e], u1 = eattr[2 * e + 1];
        const int src = eidx[e]       - g * P_N;
        const int dst = eidx[E_N + e] - g * P_N;
        atomicAdd(&degS[dst], 1);
        float p0 = u0 * (KS_C - 1), p1 = u1 * (KS_C - 1);
        float l0 = fminf(fmaxf(floorf(p0), 0.0f), (float)(KS_C - 1));
        float l1 = fminf(fmaxf(floorf(p1), 0.0f), (float)(KS_C - 1));
        float f0 = p0 - l0, f1 = p1 - l1;
        int i00 = (int)l0, i01 = min(i00 + 1, KS_C - 1);
        int i10 = (int)l1, i11 = min(i10 + 1, KS_C - 1);
        const float wa[2] = {1.0f - f0, f0};  const int ia[2] = {i00, i01};
        const float wb[2] = {1.0f - f1, f1};  const int ib[2] = {i10, i11};
        const float xv = xs[src];
        #pragma unroll
        for (int a = 0; a < 2; a++)
            #pragma unroll
            for (int b = 0; b < 2; b++) {
                const int slot = el * 4 + a * 2 + b;
                const int k = ia[a] + KS_C * ib[b];
                const int key = k * P_N + dst;
                skey[slot] = (unsigned short)key;
                ssr [slot] = (unsigned char)src;
                const float wv = wa[a] * wb[b];
                swt [slot] = wv;
                atomicAdd(&cnt[key], 1);
                atomicAdd(&sdk[key], wv * xv);
            }
    }
    __syncthreads();

    // ---- two-level exclusive scan over 1875 buckets
    if (tid < 235) {
        int s = 0;
        #pragma unroll
        for (int j = 0; j < 8; j++) { int idx = tid * 8 + j; if (idx < NKEY) s += cnt[idx]; }
        part[tid] = s;
    }
    __syncthreads();
    if (tid == 0) {
        int run = 0;
        for (int j = 0; j < 235; j++) { int t = part[j]; part[j] = run; run += t; }
    }
    __syncthreads();
    if (tid < 235) {
        int base = part[tid];
        #pragma unroll
        for (int j = 0; j < 8; j++) {
            int idx = tid * 8 + j;
            if (idx < NKEY) { int c2 = cnt[idx]; cnt[idx] = base; base += c2; }
        }
    }
    __syncthreads();
    for (int t = tid; t < NKEY; t += NTC) off2[t] = (unsigned short)cnt[t];
    if (tid == 0) off2[NKEY] = (unsigned short)RPG;
    __syncthreads();

    // ---- scatter records to gmem (sorted by (k,dst)) + conv1 from sdk
    float* gwm = d_wArr + g * RPG;
    unsigned char* gsm = d_sArr + g * RPG;
    for (int slot = tid; slot < RPG; slot += NTC) {
        const int key = skey[slot];
        const int p = atomicAdd(&cnt[key], 1);
        gwm[p] = swt[slot];
        gsm[p] = ssr[slot];
    }
    for (int it = tid; it < P_N * 32; it += NTC) {
        const int d = it >> 5, o = it & 31;
        float acc = 0.0f;
        #pragma unroll
        for (int k = 0; k < KK_C; k++) acc += sdk[k * P_N + d] * W1s[k * 32 + o];
        const float inv = 1.0f / (float)max(degS[d], 1);
        hcur[d * HQ + o] = elu_f(acc * inv + xs[d] * r1s[o] + b1s[o]);
    }

    // ---- conv layers (each begins and ends with __syncthreads)
    conv_phase<32>(sm, W32hi, W32lo, b2, gwm, gsm, tid);
    conv_phase<64>(sm, W64hi, W64lo, b3, gwm, gsm, tid);

    // ---- head: voxel max-pool + fc1/ELU + fc2 + log_softmax
    int*   vox = (int*)(sm + SM_C);
    float* gx  = (float*)(sm + SM_C + 304);
    float* f1  = (float*)(sm + SM_C + 1328);
    float* lg  = (float*)(sm + SM_C + 1840);

    if (tid < P_N) {
        const float p0 = pos[(g * P_N + tid) * 2 + 0];
        const float p1 = pos[(g * P_N + tid) * 2 + 1];
        const int v0 = min(max((int)(p0 / 14.0f), 0), 1);
        const int v1 = min(max((int)(p1 / 14.0f), 0), 1);
        vox[tid] = v0 + 2 * v1;
    }
    __syncthreads();
    if (tid < 256) {
        const int v = tid >> 6, c = tid & 63;
        float m = -3.402823466e38f; bool found = false;
        for (int r = 0; r < P_N; r++)
            if (vox[r] == v) { m = fmaxf(m, hcur[r * HQ + c]); found = true; }
        gx[v * 64 + c] = found ? m : 0.0f;
    }
    __syncthreads();
    if (tid < 128) {
        float a = fc1b[tid];
        #pragma unroll 8
        for (int i = 0; i < 256; i++) a = fmaf(gx[i], fc1w[i * 128 + tid], a);
        f1[tid] = elu_f(a);
    }
    __syncthreads();
    if (tid < 10) {
        float a = fc2b[tid];
        #pragma unroll 8
        for (int i = 0; i < 128; i++) a = fmaf(f1[i], fc2w[i * 10 + tid], a);
        lg[tid] = a;
    }
    __syncthreads();
    if (tid == 0) {
        float m = lg[0];
        for (int o = 1; o < 10; o++) m = fmaxf(m, lg[o]);
        float s = 0.0f;
        for (int o = 0; o < 10; o++) s += expf(lg[o] - m);
        const float lse = m + logf(s);
        for (int o = 0; o < 10; o++) out[g * 10 + o] = lg[o] - lse;
    }
}

// ---------------------------------------------------------------------------
// Launch
// ---------------------------------------------------------------------------
extern "C" void kernel_launch(void* const* d_in, const int* in_sizes, int n_in,
                              void* d_out, int out_size) {
    const float* x     = (const float*)d_in[0];
    const int*   eidx  = (const int*)  d_in[1];
    const float* eattr = (const float*)d_in[2];
    const float* pos   = (const float*)d_in[4];
    const float* W1    = (const float*)d_in[5];
    const float* root1 = (const float*)d_in[6];
    const float* b1    = (const float*)d_in[7];
    const float* W2    = (const float*)d_in[8];
    const float* root2 = (const float*)d_in[9];
    const float* b2    = (const float*)d_in[10];
    const float* W3    = (const float*)d_in[11];
    const float* root3 = (const float*)d_in[12];
    const float* b3    = (const float*)d_in[13];
    const float* fc1w  = (const float*)d_in[14];
    const float* fc1b  = (const float*)d_in[15];
    const float* fc2w  = (const float*)d_in[16];
    const float* fc2b  = (const float*)d_in[17];
    float* out = (float*)d_out;

    void *w32h = nullptr, *w32l = nullptr, *w64h = nullptr, *w64l = nullptr;
    cudaGetSymbolAddress(&w32h, d_W32hi);
    cudaGetSymbolAddress(&w32l, d_W32lo);
    cudaGetSymbolAddress(&w64h, d_W64hi);
    cudaGetSymbolAddress(&w64l, d_W64lo);

    cudaFuncSetAttribute(mega_kernel, cudaFuncAttributeMaxDynamicSharedMemorySize, SM_TOTAL);

    prep_kernel<<<26, 256>>>(W2, root2, (unsigned*)w32h, (unsigned*)w32l, 32, WP32);
    prep_kernel<<<26, 256>>>(W3, root3, (unsigned*)w64h, (unsigned*)w64l, 64, WP64);
    mega_kernel<<<G_NUM, NTC, SM_TOTAL>>>(
        x, eidx, eattr, pos, W1, root1, b1,
        (const unsigned*)w32h, (const unsigned*)w32l, b2,
        (const unsigned*)w64h, (const unsigned*)w64l, b3,
        fc1w, fc1b, fc2w, fc2b, out);
}

// round 12
// speedup vs baseline: 1.8583x; 1.0265x over previous
#include <cuda_runtime.h>
#include <cuda_bf16.h>
#include <math.h>
#include <stdint.h>

// ---------------------------------------------------------------------------
// Problem constants
// ---------------------------------------------------------------------------
#define G_NUM  1024
#define P_N    75
#define DEG_E  8
#define N_N    (G_NUM * P_N)
#define E_N    (N_N * DEG_E)
#define EPG    (P_N * DEG_E)          // 600 edges/graph
#define RPG    (EPG * 4)              // 2400 records/graph
#define KS_C   5
#define KK_C   25
#define NKEY   (P_N * KK_C)           // 1875 (k,dst) buckets
#define NOFF   (NKEY + 1)
#define YP     132                    // Y row stride (floats), 132 % 8 == 4
#define HQ     68                     // hcur row stride (floats), 68 % 8 == 4
#define SLAB2  1216
#define NTC    320
#define WP32   20
#define WP64   36

// ---- smem layout (byte offsets) -------------------------------------------
#define SM_OFF2  0                    // ushort[NOFF]            3752
#define SM_DEG   3760                 // int[P_N]                 300
#define SM_HCUR  4064                 // float[80*HQ]           21760
#define SM_Y     25824                // float[80*YP]           42240
#define SM_W     68064                // u32[2*2*64*WP64]       36864
#define SM_C     104928               // slab / W1 / head        6080
#define SM_TOTAL 111104

// bucket-phase aliases inside the Y region
#define BK_SWT   (SM_Y + 0)           // float[RPG]   9600
#define BK_CNT   (SM_Y + 9600)        // int[NKEY]    7500
#define BK_SDK   (SM_Y + 17100)       // float[NKEY]  7500
#define BK_KEY   (SM_Y + 24600)       // u16[RPG]     4800
#define BK_SSR   (SM_Y + 29400)       // u8[RPG]      2400
#define BK_PART  (SM_Y + 31800)       // int[240]      960
#define BK_XS    (SM_Y + 32760)       // float[80]     320

// ---------------------------------------------------------------------------
// Device scratch
// ---------------------------------------------------------------------------
__device__ float          d_wArr[G_NUM * RPG];
__device__ unsigned char  d_sArr[G_NUM * RPG];
__device__ __align__(16) unsigned d_W32hi[26 * 64 * WP32];
__device__ __align__(16) unsigned d_W32lo[26 * 64 * WP32];
__device__ __align__(16) unsigned d_W64hi[26 * 64 * WP64];
__device__ __align__(16) unsigned d_W64lo[26 * 64 * WP64];

__device__ __forceinline__ float elu_f(float v) { return v > 0.0f ? v : expm1f(v); }

__device__ __forceinline__ unsigned pk2(float a, float b) {
    __nv_bfloat162 t = __floats2bfloat162_rn(a, b);
    return reinterpret_cast<unsigned&>(t);
}
__device__ __forceinline__ float bhi(float v) {
    return __bfloat162float(__float2bfloat16(v));
}

__device__ __forceinline__ uint32_t smem_to_u32(const void* p) {
    uint32_t a;
    asm("{ .reg .u64 t; cvta.to.shared.u64 t, %1; cvt.u32.u64 %0, t; }"
        : "=r"(a) : "l"(p));
    return a;
}

#define CP_ASYNC16(dst, src) \
    asm volatile("cp.async.ca.shared.global [%0], [%1], 16;" \
                 :: "r"((uint32_t)(dst)), "l"(src) : "memory")
#define CP_ASYNC4(dst, src) \
    asm volatile("cp.async.ca.shared.global [%0], [%1], 4;" \
                 :: "r"((uint32_t)(dst)), "l"(src) : "memory")
#define CP_WAIT_ALL() asm volatile("cp.async.wait_all;" ::: "memory")

__device__ __forceinline__ void mma_bf16(float c[4], const unsigned a[4],
                                         unsigned b0, unsigned b1) {
    asm volatile(
        "mma.sync.aligned.m16n8k16.row.col.f32.bf16.bf16.f32 "
        "{%0,%1,%2,%3}, {%4,%5,%6,%7}, {%8,%9}, {%0,%1,%2,%3};"
        : "+f"(c[0]), "+f"(c[1]), "+f"(c[2]), "+f"(c[3])
        : "r"(a[0]), "r"(a[1]), "r"(a[2]), "r"(a[3]), "r"(b0), "r"(b1));
}

// ---------------------------------------------------------------------------
// Prep: split W (+root) into bf16 hi/lo, transposed [mat][o][ipair]
// ---------------------------------------------------------------------------
__global__ __launch_bounds__(256)
void prep_kernel(const float* __restrict__ W, const float* __restrict__ root,
                 unsigned* __restrict__ oHi, unsigned* __restrict__ oLo,
                 int I, int WPv) {
    const int mat = blockIdx.x;
    const float* Wp = (mat < KK_C) ? (W + mat * I * 64) : root;
    const int KHv = I / 2;
    for (int t = threadIdx.x; t < 64 * KHv; t += 256) {
        const int o = t & 63, ipair = t >> 6;
        float w0 = Wp[(2 * ipair) * 64 + o], w1 = Wp[(2 * ipair + 1) * 64 + o];
        float h0 = bhi(w0), h1 = bhi(w1);
        oHi[(mat * 64 + o) * WPv + ipair] = pk2(h0, h1);
        oLo[(mat * 64 + o) * WPv + ipair] = pk2(w0 - h0, w1 - h1);
    }
    for (int t = threadIdx.x; t < 64 * (WPv - KHv); t += 256) {
        const int o = t % 64, p = KHv + t / 64;
        oHi[(mat * 64 + o) * WPv + p] = 0;
        oLo[(mat * 64 + o) * WPv + p] = 0;
    }
}

// ---------------------------------------------------------------------------
// Conv phase (I in {32,64}): chunk = 2 mats; 3 independent mma chains;
// cp.async for W staging + slab weights.
// ---------------------------------------------------------------------------
template<int I>
__device__ __forceinline__
void conv_phase(char* sm, uint32_t sm32, const unsigned* __restrict__ gWhi,
                const unsigned* __restrict__ gWlo, const float* __restrict__ bias,
                const float* __restrict__ gw, const unsigned char* __restrict__ gs,
                int tid) {
    constexpr int KH  = I / 2;
    constexpr int KST = I / 16;
    constexpr int WP  = KH + 4;
    constexpr int WCH = 2 * 64 * WP;

    unsigned short* off2 = (unsigned short*)(sm + SM_OFF2);
    int*            degS = (int*)(sm + SM_DEG);
    float*          hcur = (float*)(sm + SM_HCUR);
    float*          Ys   = (float*)(sm + SM_Y);
    unsigned*       wsHi = (unsigned*)(sm + SM_W);
    unsigned*       wsLo = wsHi + WCH;
    float*          slw  = (float*)(sm + SM_C);
    unsigned char*  sls  = (unsigned char*)(sm + SM_C + 4864);

    const uint32_t wsHiA = sm32 + SM_W;
    const uint32_t wsLoA = wsHiA + WCH * 4;
    const uint32_t slwA  = sm32 + SM_C;

    __syncthreads();   // hcur ready; Y/W/slab regions free

    // stage W chunk 0 via cp.async
    for (int t = tid; t < WCH / 4; t += NTC) {
        CP_ASYNC16(wsHiA + 16 * t, (const uint4*)gWhi + t);
        CP_ASYNC16(wsLoA + 16 * t, (const uint4*)gWlo + t);
    }

    const int w = tid >> 5, lane = tid & 31;
    const int gr = lane >> 2, cg = lane & 3;
    const int mt = w >> 1, matw = w & 1;
    const int r0 = mt * 16 + gr;
    const int d = tid >> 2, q = tid & 3;

    // A fragments straight from fp32 hcur (conflict-free HQ % 8 == 4)
    unsigned aHi[KST][4], aLo[KST][4];
    #pragma unroll
    for (int ks = 0; ks < KST; ks++) {
        const int p0 = ks * 8 + cg;
        float2 v00 = *(const float2*)(hcur + r0 * HQ + 2 * p0);
        float2 v10 = *(const float2*)(hcur + (r0 + 8) * HQ + 2 * p0);
        float2 v01 = *(const float2*)(hcur + r0 * HQ + 2 * p0 + 8);
        float2 v11 = *(const float2*)(hcur + (r0 + 8) * HQ + 2 * p0 + 8);
        float a, b;
        a = bhi(v00.x); b = bhi(v00.y);
        aHi[ks][0] = pk2(a, b); aLo[ks][0] = pk2(v00.x - a, v00.y - b);
        a = bhi(v10.x); b = bhi(v10.y);
        aHi[ks][1] = pk2(a, b); aLo[ks][1] = pk2(v10.x - a, v10.y - b);
        a = bhi(v01.x); b = bhi(v01.y);
        aHi[ks][2] = pk2(a, b); aLo[ks][2] = pk2(v01.x - a, v01.y - b);
        a = bhi(v11.x); b = bhi(v11.y);
        aHi[ks][3] = pk2(a, b); aLo[ks][3] = pk2(v11.x - a, v11.y - b);
    }
    CP_WAIT_ALL();
    __syncthreads();   // W0 staged

    float agg[16];
    #pragma unroll
    for (int j = 0; j < 16; j++) agg[j] = 0.0f;

    for (int c = 0; c < 13; c++) {
        // phase A: slab prefetch (cp.async weights, scalar srcs) + GEMM(c)
        const int base = off2[(2 * c) * P_N];
        const int endi = min((2 * c + 2) * P_N, NKEY);
        const int nrec = (int)off2[endi] - base;
        for (int t = tid; t < nrec; t += NTC)
            CP_ASYNC4(slwA + 4 * t, gw + base + t);
        for (int t = tid; t < nrec; t += NTC)
            sls[t] = gs[base + t];

        #pragma unroll
        for (int j = 0; j < 8; j++) {
            const int n0 = j * 8;
            const unsigned* bh = wsHi + (matw * 64 + n0 + gr) * WP;
            const unsigned* bl = wsLo + (matw * 64 + n0 + gr) * WP;
            float Ca[4] = {0, 0, 0, 0}, Cb[4] = {0, 0, 0, 0}, Cc[4] = {0, 0, 0, 0};
            #pragma unroll
            for (int ks = 0; ks < KST; ks++) {
                const int p0 = ks * 8 + cg;
                const unsigned b0h = bh[p0], b1h = bh[p0 + 4];
                const unsigned b0l = bl[p0], b1l = bl[p0 + 4];
                mma_bf16(Ca, aHi[ks], b0h, b1h);
                mma_bf16(Cb, aLo[ks], b0h, b1h);
                mma_bf16(Cc, aHi[ks], b0l, b1l);
            }
            float* yp = Ys + r0 * YP + matw * 64 + n0 + 2 * cg;
            *(float2*)yp            = make_float2(Ca[0] + Cb[0] + Cc[0],
                                                  Ca[1] + Cb[1] + Cc[1]);
            *(float2*)(yp + 8 * YP) = make_float2(Ca[2] + Cb[2] + Cc[2],
                                                  Ca[3] + Cb[3] + Cc[3]);
        }
        CP_WAIT_ALL();
        __syncthreads();   // Y + slab ready; Ws free

        // phase B: gather(c) + stage W(c+1) via cp.async
        if (c < 12) {
            const uint4* sH = (const uint4*)(gWhi + (2 * (c + 1)) * (64 * WP));
            const uint4* sL = (const uint4*)(gWlo + (2 * (c + 1)) * (64 * WP));
            for (int t = tid; t < WCH / 4; t += NTC) {
                CP_ASYNC16(wsHiA + 16 * t, sH + t);
                CP_ASYNC16(wsLoA + 16 * t, sL + t);
            }
        }
        if (d < P_N) {
            #pragma unroll
            for (int mm = 0; mm < 2; mm++) {
                const int gk = 2 * c + mm;
                if (gk < KK_C) {
                    const int lo = (int)off2[gk * P_N + d] - base;
                    const int hi = (int)off2[gk * P_N + d + 1] - base;
                    const float* yq = Ys + mm * 64 + q * 16;
                    for (int r = lo; r < hi; r++) {
                        const float wv = slw[r];
                        const float4* yp = (const float4*)(yq + (int)sls[r] * YP);
                        #pragma unroll
                        for (int jj = 0; jj < 4; jj++) {
                            float4 v = yp[jj];
                            agg[4 * jj + 0] = fmaf(wv, v.x, agg[4 * jj + 0]);
                            agg[4 * jj + 1] = fmaf(wv, v.y, agg[4 * jj + 1]);
                            agg[4 * jj + 2] = fmaf(wv, v.z, agg[4 * jj + 2]);
                            agg[4 * jj + 3] = fmaf(wv, v.w, agg[4 * jj + 3]);
                        }
                    }
                }
            }
        }
        CP_WAIT_ALL();
        __syncthreads();   // Ws(c+1) ready; gather done -> Y reusable
    }

    // epilogue: mean-scale + root (chunk 12, mat slot 1) + bias + ELU -> hcur
    if (d < P_N) {
        const float inv = 1.0f / (float)max(degS[d], 1);
        const float4* rt = (const float4*)(Ys + d * YP + 64 + q * 16);
        float* op = hcur + d * HQ + q * 16;
        #pragma unroll
        for (int jj = 0; jj < 4; jj++) {
            float4 r4 = rt[jj];
            float4 o4;
            o4.x = elu_f(agg[4 * jj + 0] * inv + r4.x + bias[q * 16 + 4 * jj + 0]);
            o4.y = elu_f(agg[4 * jj + 1] * inv + r4.y + bias[q * 16 + 4 * jj + 1]);
            o4.z = elu_f(agg[4 * jj + 2] * inv + r4.z + bias[q * 16 + 4 * jj + 2]);
            o4.w = elu_f(agg[4 * jj + 3] * inv + r4.w + bias[q * 16 + 4 * jj + 3]);
            *(float4*)(op + 4 * jj) = o4;
        }
    }
    __syncthreads();
}

// ---------------------------------------------------------------------------
// Mega kernel: one CTA = one graph, end to end.
// ---------------------------------------------------------------------------
__global__ __launch_bounds__(NTC, 2)
void mega_kernel(const float* __restrict__ x, const int* __restrict__ eidx,
                 const float* __restrict__ eattr, const float* __restrict__ pos,
                 const float* __restrict__ W1, const float* __restrict__ root1,
                 const float* __restrict__ b1,
                 const unsigned* __restrict__ W32hi, const unsigned* __restrict__ W32lo,
                 const float* __restrict__ b2,
                 const unsigned* __restrict__ W64hi, const unsigned* __restrict__ W64lo,
                 const float* __restrict__ b3,
                 const float* __restrict__ fc1w, const float* __restrict__ fc1b,
                 const float* __restrict__ fc2w, const float* __restrict__ fc2b,
                 float* __restrict__ out) {
    extern __shared__ __align__(16) char sm[];
    const int g = blockIdx.x, tid = threadIdx.x;
    const uint32_t sm32 = smem_to_u32(sm);

    unsigned short* off2 = (unsigned short*)(sm + SM_OFF2);
    int*            degS = (int*)(sm + SM_DEG);
    float*          hcur = (float*)(sm + SM_HCUR);
    float*          swt  = (float*)(sm + BK_SWT);
    int*            cnt  = (int*)(sm + BK_CNT);
    float*          sdk  = (float*)(sm + BK_SDK);
    unsigned short* skey = (unsigned short*)(sm + BK_KEY);
    unsigned char*  ssr  = (unsigned char*)(sm + BK_SSR);
    int*            part = (int*)(sm + BK_PART);
    float*          xs   = (float*)(sm + BK_XS);
    float*          W1s  = (float*)(sm + SM_C);
    float*          r1s  = (float*)(sm + SM_C + 3200);
    float*          b1s  = (float*)(sm + SM_C + 3328);

    // ---- init
    for (int t = tid; t < NKEY; t += NTC) { cnt[t] = 0; sdk[t] = 0.0f; }
    if (tid < P_N) { degS[tid] = 0; xs[tid] = x[g * P_N + tid]; }
    for (int t = tid; t < 5 * HQ; t += NTC) hcur[P_N * HQ + t] = 0.0f;
    for (int t = tid; t < KK_C * 32; t += NTC) W1s[t] = W1[t];
    if (tid < 32) { r1s[tid] = root1[tid]; b1s[tid] = b1[tid]; }
    __syncthreads();

    // ---- bucket: basis + records + counts + sdk (conv1 partial sums)
    for (int el = tid; el < EPG; el += NTC) {
        const int e  = g * EPG + el;
        const float u0 = eattr[2 * e], u1 = eattr[2 * e + 1];
        const int src = eidx[e]       - g * P_N;
        const int dst = eidx[E_N + e] - g * P_N;
        atomicAdd(&degS[dst], 1);
        float p0 = u0 * (KS_C - 1), p1 = u1 * (KS_C - 1);
        float l0 = fminf(fmaxf(floorf(p0), 0.0f), (float)(KS_C - 1));
        float l1 = fminf(fmaxf(floorf(p1), 0.0f), (float)(KS_C - 1));
        float f0 = p0 - l0, f1 = p1 - l1;
        int i00 = (int)l0, i01 = min(i00 + 1, KS_C - 1);
        int i10 = (int)l1, i11 = min(i10 + 1, KS_C - 1);
        const float wa[2] = {1.0f - f0, f0};  const int ia[2] = {i00, i01};
        const float wb[2] = {1.0f - f1, f1};  const int ib[2] = {i10, i11};
        const float xv = xs[src];
        #pragma unroll
        for (int a = 0; a < 2; a++)
            #pragma unroll
            for (int b = 0; b < 2; b++) {
                const int slot = el * 4 + a * 2 + b;
                const int k = ia[a] + KS_C * ib[b];
                const int key = k * P_N + dst;
                skey[slot] = (unsigned short)key;
                ssr [slot] = (unsigned char)src;
                const float wv = wa[a] * wb[b];
                swt [slot] = wv;
                atomicAdd(&cnt[key], 1);
                atomicAdd(&sdk[key], wv * xv);
            }
    }
    __syncthreads();

    // ---- two-level exclusive scan
    if (tid < 235) {
        int s = 0;
        #pragma unroll
        for (int j = 0; j < 8; j++) { int idx = tid * 8 + j; if (idx < NKEY) s += cnt[idx]; }
        part[tid] = s;
    }
    __syncthreads();
    if (tid == 0) {
        int run = 0;
        for (int j = 0; j < 235; j++) { int t = part[j]; part[j] = run; run += t; }
    }
    __syncthreads();
    if (tid < 235) {
        int base = part[tid];
        #pragma unroll
        for (int j = 0; j < 8; j++) {
            int idx = tid * 8 + j;
            if (idx < NKEY) { int c2 = cnt[idx]; cnt[idx] = base; base += c2; }
        }
    }
    __syncthreads();
    for (int t = tid; t < NKEY; t += NTC) off2[t] = (unsigned short)cnt[t];
    if (tid == 0) off2[NKEY] = (unsigned short)RPG;
    __syncthreads();

    // ---- scatter records to gmem + conv1 from sdk
    float* gwm = d_wArr + g * RPG;
    unsigned char* gsm = d_sArr + g * RPG;
    for (int slot = tid; slot < RPG; slot += NTC) {
        const int key = skey[slot];
        const int p = atomicAdd(&cnt[key], 1);
        gwm[p] = swt[slot];
        gsm[p] = ssr[slot];
    }
    for (int it = tid; it < P_N * 32; it += NTC) {
        const int d = it >> 5, o = it & 31;
        float acc = 0.0f;
        #pragma unroll
        for (int k = 0; k < KK_C; k++) acc += sdk[k * P_N + d] * W1s[k * 32 + o];
        const float inv = 1.0f / (float)max(degS[d], 1);
        hcur[d * HQ + o] = elu_f(acc * inv + xs[d] * r1s[o] + b1s[o]);
    }

    // ---- conv layers
    conv_phase<32>(sm, sm32, W32hi, W32lo, b2, gwm, gsm, tid);
    conv_phase<64>(sm, sm32, W64hi, W64lo, b3, gwm, gsm, tid);

    // ---- head
    int*   vox = (int*)(sm + SM_C);
    float* gx  = (float*)(sm + SM_C + 304);
    float* f1  = (float*)(sm + SM_C + 1328);
    float* lg  = (float*)(sm + SM_C + 1840);

    if (tid < P_N) {
        const float p0 = pos[(g * P_N + tid) * 2 + 0];
        const float p1 = pos[(g * P_N + tid) * 2 + 1];
        const int v0 = min(max((int)(p0 / 14.0f), 0), 1);
        const int v1 = min(max((int)(p1 / 14.0f), 0), 1);
        vox[tid] = v0 + 2 * v1;
    }
    __syncthreads();
    if (tid < 256) {
        const int v = tid >> 6, c = tid & 63;
        float m = -3.402823466e38f; bool found = false;
        for (int r = 0; r < P_N; r++)
            if (vox[r] == v) { m = fmaxf(m, hcur[r * HQ + c]); found = true; }
        gx[v * 64 + c] = found ? m : 0.0f;
    }
    __syncthreads();
    if (tid < 128) {
        float a = fc1b[tid];
        #pragma unroll 8
        for (int i = 0; i < 256; i++) a = fmaf(gx[i], fc1w[i * 128 + tid], a);
        f1[tid] = elu_f(a);
    }
    __syncthreads();
    if (tid < 10) {
        float a = fc2b[tid];
        #pragma unroll 8
        for (int i = 0; i < 128; i++) a = fmaf(f1[i], fc2w[i * 10 + tid], a);
        lg[tid] = a;
    }
    __syncthreads();
    if (tid == 0) {
        float m = lg[0];
        for (int o = 1; o < 10; o++) m = fmaxf(m, lg[o]);
        float s = 0.0f;
        for (int o = 0; o < 10; o++) s += expf(lg[o] - m);
        const float lse = m + logf(s);
        for (int o = 0; o < 10; o++) out[g * 10 + o] = lg[o] - lse;
    }
}

// ---------------------------------------------------------------------------
// Launch
// ---------------------------------------------------------------------------
extern "C" void kernel_launch(void* const* d_in, const int* in_sizes, int n_in,
                              void* d_out, int out_size) {
    const float* x     = (const float*)d_in[0];
    const int*   eidx  = (const int*)  d_in[1];
    const float* eattr = (const float*)d_in[2];
    const float* pos   = (const float*)d_in[4];
    const float* W1    = (const float*)d_in[5];
    const float* root1 = (const float*)d_in[6];
    const float* b1    = (const float*)d_in[7];
    const float* W2    = (const float*)d_in[8];
    const float* root2 = (const float*)d_in[9];
    const float* b2    = (const float*)d_in[10];
    const float* W3    = (const float*)d_in[11];
    const float* root3 = (const float*)d_in[12];
    const float* b3    = (const float*)d_in[13];
    const float* fc1w  = (const float*)d_in[14];
    const float* fc1b  = (const float*)d_in[15];
    const float* fc2w  = (const float*)d_in[16];
    const float* fc2b  = (const float*)d_in[17];
    float* out = (float*)d_out;

    void *w32h = nullptr, *w32l = nullptr, *w64h = nullptr, *w64l = nullptr;
    cudaGetSymbolAddress(&w32h, d_W32hi);
    cudaGetSymbolAddress(&w32l, d_W32lo);
    cudaGetSymbolAddress(&w64h, d_W64hi);
    cudaGetSymbolAddress(&w64l, d_W64lo);

    cudaFuncSetAttribute(mega_kernel, cudaFuncAttributeMaxDynamicSharedMemorySize, SM_TOTAL);

    prep_kernel<<<26, 256>>>(W2, root2, (unsigned*)w32h, (unsigned*)w32l, 32, WP32);
    prep_kernel<<<26, 256>>>(W3, root3, (unsigned*)w64h, (unsigned*)w64l, 64, WP64);
    mega_kernel<<<G_NUM, NTC, SM_TOTAL>>>(
        x, eidx, eattr, pos, W1, root1, b1,
        (const unsigned*)w32h, (const unsigned*)w32l, b2,
        (const unsigned*)w64h, (const unsigned*)w64l, b3,
        fc1w, fc1b, fc2w, fc2b, out);
}

// round 13
// speedup vs baseline: 1.9643x; 1.0570x over previous
#include <cuda_runtime.h>
#include <cuda_bf16.h>
#include <math.h>
#include <stdint.h>

// ---------------------------------------------------------------------------
// Problem constants
// ---------------------------------------------------------------------------
#define G_NUM  1024
#define P_N    75
#define DEG_E  8
#define N_N    (G_NUM * P_N)
#define E_N    (N_N * DEG_E)
#define EPG    (P_N * DEG_E)          // 600 edges/graph
#define RPG    (EPG * 4)              // 2400 records/graph
#define KS_C   5
#define KK_C   25
#define NKEY   (P_N * KK_C)           // 1875 (k,dst) buckets
#define NOFF   (NKEY + 1)
#define YP     132                    // Y row stride (floats), 132 % 8 == 4
#define HQ     68                     // hcur row stride (floats), 68 % 8 == 4
#define SLAB2  1216
#define NTC    320
#define WP32   20
#define WP64   36

// ---- smem layout (byte offsets) -------------------------------------------
#define SM_OFF2  0                    // ushort[NOFF]            3752
#define SM_DEG   3760                 // int[P_N]                 300
#define SM_HCUR  4064                 // float[80*HQ]           21760
#define SM_Y     25824                // float[80*YP]           42240
#define SM_W     68064                // u32[2*2*64*WP64]       36864
#define SM_C     104928               // slab(uint2) / W1 / head 9728
#define SM_TOTAL 114688

// bucket-phase aliases inside the Y region
#define BK_SWT   (SM_Y + 0)           // float[RPG]   9600
#define BK_CNT   (SM_Y + 9600)        // int[NKEY]    7500
#define BK_SDK   (SM_Y + 17100)       // float[NKEY]  7500
#define BK_KEY   (SM_Y + 24600)       // u16[RPG]     4800
#define BK_SSR   (SM_Y + 29400)       // u8[RPG]      2400
#define BK_PART  (SM_Y + 31800)       // int[240]      960
#define BK_XS    (SM_Y + 32760)       // float[80]     320

// ---------------------------------------------------------------------------
// Device scratch
// ---------------------------------------------------------------------------
__device__ __align__(16) uint2 d_rec[G_NUM * RPG];   // {w bits, src}, (k,dst)-sorted
__device__ __align__(16) unsigned d_W32hi[26 * 64 * WP32];
__device__ __align__(16) unsigned d_W32lo[26 * 64 * WP32];
__device__ __align__(16) unsigned d_W64hi[26 * 64 * WP64];
__device__ __align__(16) unsigned d_W64lo[26 * 64 * WP64];

__device__ __forceinline__ float elu_f(float v) { return v > 0.0f ? v : expm1f(v); }

__device__ __forceinline__ unsigned pk2(float a, float b) {
    __nv_bfloat162 t = __floats2bfloat162_rn(a, b);
    return reinterpret_cast<unsigned&>(t);
}
__device__ __forceinline__ float bhi(float v) {
    return __bfloat162float(__float2bfloat16(v));
}

__device__ __forceinline__ uint32_t smem_to_u32(const void* p) {
    uint32_t a;
    asm("{ .reg .u64 t; cvta.to.shared.u64 t, %1; cvt.u32.u64 %0, t; }"
        : "=r"(a) : "l"(p));
    return a;
}

#define CP_ASYNC16(dst, src) \
    asm volatile("cp.async.ca.shared.global [%0], [%1], 16;" \
                 :: "r"((uint32_t)(dst)), "l"(src) : "memory")
#define CP_ASYNC8(dst, src) \
    asm volatile("cp.async.ca.shared.global [%0], [%1], 8;" \
                 :: "r"((uint32_t)(dst)), "l"(src) : "memory")
#define CP_WAIT_ALL() asm volatile("cp.async.wait_all;" ::: "memory")

__device__ __forceinline__ void mma_bf16(float c[4], const unsigned a[4],
                                         unsigned b0, unsigned b1) {
    asm volatile(
        "mma.sync.aligned.m16n8k16.row.col.f32.bf16.bf16.f32 "
        "{%0,%1,%2,%3}, {%4,%5,%6,%7}, {%8,%9}, {%0,%1,%2,%3};"
        : "+f"(c[0]), "+f"(c[1]), "+f"(c[2]), "+f"(c[3])
        : "r"(a[0]), "r"(a[1]), "r"(a[2]), "r"(a[3]), "r"(b0), "r"(b1));
}

// ---------------------------------------------------------------------------
// Prep: split W (+root) into bf16 hi/lo, transposed [mat][o][ipair]
// ---------------------------------------------------------------------------
__global__ __launch_bounds__(256)
void prep_kernel(const float* __restrict__ W, const float* __restrict__ root,
                 unsigned* __restrict__ oHi, unsigned* __restrict__ oLo,
                 int I, int WPv) {
    const int mat = blockIdx.x;
    const float* Wp = (mat < KK_C) ? (W + mat * I * 64) : root;
    const int KHv = I / 2;
    for (int t = threadIdx.x; t < 64 * KHv; t += 256) {
        const int o = t & 63, ipair = t >> 6;
        float w0 = Wp[(2 * ipair) * 64 + o], w1 = Wp[(2 * ipair + 1) * 64 + o];
        float h0 = bhi(w0), h1 = bhi(w1);
        oHi[(mat * 64 + o) * WPv + ipair] = pk2(h0, h1);
        oLo[(mat * 64 + o) * WPv + ipair] = pk2(w0 - h0, w1 - h1);
    }
    for (int t = threadIdx.x; t < 64 * (WPv - KHv); t += 256) {
        const int o = t % 64, p = KHv + t / 64;
        oHi[(mat * 64 + o) * WPv + p] = 0;
        oLo[(mat * 64 + o) * WPv + p] = 0;
    }
}

// ---------------------------------------------------------------------------
// Conv phase (I in {32,64}): chunk = 2 mats; 3 independent mma chains;
// cp.async staging; uint2 records; software-pipelined gather.
// ---------------------------------------------------------------------------
template<int I>
__device__ __forceinline__
void conv_phase(char* sm, uint32_t sm32, const unsigned* __restrict__ gWhi,
                const unsigned* __restrict__ gWlo, const float* __restrict__ bias,
                const uint2* __restrict__ grec, int tid) {
    constexpr int KH  = I / 2;
    constexpr int KST = I / 16;
    constexpr int WP  = KH + 4;
    constexpr int WCH = 2 * 64 * WP;

    unsigned short* off2 = (unsigned short*)(sm + SM_OFF2);
    int*            degS = (int*)(sm + SM_DEG);
    float*          hcur = (float*)(sm + SM_HCUR);
    float*          Ys   = (float*)(sm + SM_Y);
    unsigned*       wsHi = (unsigned*)(sm + SM_W);
    unsigned*       wsLo = wsHi + WCH;
    uint2*          slab = (uint2*)(sm + SM_C);

    const uint32_t wsHiA = sm32 + SM_W;
    const uint32_t wsLoA = wsHiA + WCH * 4;
    const uint32_t slabA = sm32 + SM_C;

    __syncthreads();   // hcur ready; Y/W/slab regions free

    // stage W chunk 0 via cp.async
    for (int t = tid; t < WCH / 4; t += NTC) {
        CP_ASYNC16(wsHiA + 16 * t, (const uint4*)gWhi + t);
        CP_ASYNC16(wsLoA + 16 * t, (const uint4*)gWlo + t);
    }

    const int w = tid >> 5, lane = tid & 31;
    const int gr = lane >> 2, cg = lane & 3;
    const int mt = w >> 1, matw = w & 1;
    const int r0 = mt * 16 + gr;
    const int d = tid >> 2, q = tid & 3;

    // A fragments straight from fp32 hcur (conflict-free HQ % 8 == 4)
    unsigned aHi[KST][4], aLo[KST][4];
    #pragma unroll
    for (int ks = 0; ks < KST; ks++) {
        const int p0 = ks * 8 + cg;
        float2 v00 = *(const float2*)(hcur + r0 * HQ + 2 * p0);
        float2 v10 = *(const float2*)(hcur + (r0 + 8) * HQ + 2 * p0);
        float2 v01 = *(const float2*)(hcur + r0 * HQ + 2 * p0 + 8);
        float2 v11 = *(const float2*)(hcur + (r0 + 8) * HQ + 2 * p0 + 8);
        float a, b;
        a = bhi(v00.x); b = bhi(v00.y);
        aHi[ks][0] = pk2(a, b); aLo[ks][0] = pk2(v00.x - a, v00.y - b);
        a = bhi(v10.x); b = bhi(v10.y);
        aHi[ks][1] = pk2(a, b); aLo[ks][1] = pk2(v10.x - a, v10.y - b);
        a = bhi(v01.x); b = bhi(v01.y);
        aHi[ks][2] = pk2(a, b); aLo[ks][2] = pk2(v01.x - a, v01.y - b);
        a = bhi(v11.x); b = bhi(v11.y);
        aHi[ks][3] = pk2(a, b); aLo[ks][3] = pk2(v11.x - a, v11.y - b);
    }
    CP_WAIT_ALL();
    __syncthreads();   // W0 staged

    float agg[16];
    #pragma unroll
    for (int j = 0; j < 16; j++) agg[j] = 0.0f;

    for (int c = 0; c < 13; c++) {
        // phase A: slab prefetch (cp.async uint2 records) + GEMM(c)
        const int base = off2[(2 * c) * P_N];
        const int endi = min((2 * c + 2) * P_N, NKEY);
        const int nrec = (int)off2[endi] - base;
        for (int t = tid; t < nrec; t += NTC)
            CP_ASYNC8(slabA + 8 * t, grec + base + t);

        #pragma unroll
        for (int j = 0; j < 8; j++) {
            const int n0 = j * 8;
            const unsigned* bh = wsHi + (matw * 64 + n0 + gr) * WP;
            const unsigned* bl = wsLo + (matw * 64 + n0 + gr) * WP;
            float Ca[4] = {0, 0, 0, 0}, Cb[4] = {0, 0, 0, 0}, Cc[4] = {0, 0, 0, 0};
            #pragma unroll
            for (int ks = 0; ks < KST; ks++) {
                const int p0 = ks * 8 + cg;
                const unsigned b0h = bh[p0], b1h = bh[p0 + 4];
                const unsigned b0l = bl[p0], b1l = bl[p0 + 4];
                mma_bf16(Ca, aHi[ks], b0h, b1h);
                mma_bf16(Cb, aLo[ks], b0h, b1h);
                mma_bf16(Cc, aHi[ks], b0l, b1l);
            }
            float* yp = Ys + r0 * YP + matw * 64 + n0 + 2 * cg;
            *(float2*)yp            = make_float2(Ca[0] + Cb[0] + Cc[0],
                                                  Ca[1] + Cb[1] + Cc[1]);
            *(float2*)(yp + 8 * YP) = make_float2(Ca[2] + Cb[2] + Cc[2],
                                                  Ca[3] + Cb[3] + Cc[3]);
        }
        CP_WAIT_ALL();
        __syncthreads();   // Y + slab ready; Ws free

        // phase B: stage W(c+1) + software-pipelined gather(c)
        if (c < 12) {
            const uint4* sH = (const uint4*)(gWhi + (2 * (c + 1)) * (64 * WP));
            const uint4* sL = (const uint4*)(gWlo + (2 * (c + 1)) * (64 * WP));
            for (int t = tid; t < WCH / 4; t += NTC) {
                CP_ASYNC16(wsHiA + 16 * t, sH + t);
                CP_ASYNC16(wsLoA + 16 * t, sL + t);
            }
        }
        if (d < P_N) {
            const int kmax = (c == 12) ? 1 : 2;
            const int lo = (int)off2[(2 * c) * P_N + d] - base;
            const int mid = (int)off2[(2 * c + 1) * P_N + d] - base;  // valid: row d of mat 2c+1... see note
            // NOTE: records for (mat 2c, d) are [lo, hiA); for (mat 2c+1, d) are [loB, hiB).
            const int hiA = (int)off2[(2 * c) * P_N + d + 1] - base;
            const float* yq0 = Ys + q * 16;
            // ---- mat 2c
            int r = lo;
            if (r < hiA) {
                uint2 rc = slab[r];
                while (true) {
                    const float wv = __uint_as_float(rc.x);
                    const float4* yp = (const float4*)(yq0 + (int)rc.y * YP);
                    float4 v0 = yp[0], v1 = yp[1], v2 = yp[2], v3 = yp[3];
                    ++r;
                    if (r < hiA) rc = slab[r];
                    agg[0]  = fmaf(wv, v0.x, agg[0]);  agg[1]  = fmaf(wv, v0.y, agg[1]);
                    agg[2]  = fmaf(wv, v0.z, agg[2]);  agg[3]  = fmaf(wv, v0.w, agg[3]);
                    agg[4]  = fmaf(wv, v1.x, agg[4]);  agg[5]  = fmaf(wv, v1.y, agg[5]);
                    agg[6]  = fmaf(wv, v1.z, agg[6]);  agg[7]  = fmaf(wv, v1.w, agg[7]);
                    agg[8]  = fmaf(wv, v2.x, agg[8]);  agg[9]  = fmaf(wv, v2.y, agg[9]);
                    agg[10] = fmaf(wv, v2.z, agg[10]); agg[11] = fmaf(wv, v2.w, agg[11]);
                    agg[12] = fmaf(wv, v3.x, agg[12]); agg[13] = fmaf(wv, v3.y, agg[13]);
                    agg[14] = fmaf(wv, v3.z, agg[14]); agg[15] = fmaf(wv, v3.w, agg[15]);
                    if (r >= hiA) break;
                }
            }
            // ---- mat 2c+1 (skip on last chunk where only mat 24 exists)
            if (kmax == 2) {
                const int loB = mid;
                const int hiB = (int)off2[(2 * c + 1) * P_N + d + 1] - base;
                const float* yq1 = yq0 + 64;
                r = loB;
                if (r < hiB) {
                    uint2 rc = slab[r];
                    while (true) {
                        const float wv = __uint_as_float(rc.x);
                        const float4* yp = (const float4*)(yq1 + (int)rc.y * YP);
                        float4 v0 = yp[0], v1 = yp[1], v2 = yp[2], v3 = yp[3];
                        ++r;
                        if (r < hiB) rc = slab[r];
                        agg[0]  = fmaf(wv, v0.x, agg[0]);  agg[1]  = fmaf(wv, v0.y, agg[1]);
                        agg[2]  = fmaf(wv, v0.z, agg[2]);  agg[3]  = fmaf(wv, v0.w, agg[3]);
                        agg[4]  = fmaf(wv, v1.x, agg[4]);  agg[5]  = fmaf(wv, v1.y, agg[5]);
                        agg[6]  = fmaf(wv, v1.z, agg[6]);  agg[7]  = fmaf(wv, v1.w, agg[7]);
                        agg[8]  = fmaf(wv, v2.x, agg[8]);  agg[9]  = fmaf(wv, v2.y, agg[9]);
                        agg[10] = fmaf(wv, v2.z, agg[10]); agg[11] = fmaf(wv, v2.w, agg[11]);
                        agg[12] = fmaf(wv, v3.x, agg[12]); agg[13] = fmaf(wv, v3.y, agg[13]);
                        agg[14] = fmaf(wv, v3.z, agg[14]); agg[15] = fmaf(wv, v3.w, agg[15]);
                        if (r >= hiB) break;
                    }
                }
            }
        }
        CP_WAIT_ALL();
        __syncthreads();   // Ws(c+1) ready; gather done -> Y reusable
    }

    // epilogue: mean-scale + root (chunk 12, mat slot 1) + bias + ELU -> hcur
    if (d < P_N) {
        const float inv = 1.0f / (float)max(degS[d], 1);
        const float4* rt = (const float4*)(Ys + d * YP + 64 + q * 16);
        float* op = hcur + d * HQ + q * 16;
        #pragma unroll
        for (int jj = 0; jj < 4; jj++) {
            float4 r4 = rt[jj];
            float4 o4;
            o4.x = elu_f(agg[4 * jj + 0] * inv + r4.x + bias[q * 16 + 4 * jj + 0]);
            o4.y = elu_f(agg[4 * jj + 1] * inv + r4.y + bias[q * 16 + 4 * jj + 1]);
            o4.z = elu_f(agg[4 * jj + 2] * inv + r4.z + bias[q * 16 + 4 * jj + 2]);
            o4.w = elu_f(agg[4 * jj + 3] * inv + r4.w + bias[q * 16 + 4 * jj + 3]);
            *(float4*)(op + 4 * jj) = o4;
        }
    }
    __syncthreads();
}

// ---------------------------------------------------------------------------
// Mega kernel: one CTA = one graph, end to end.
// ---------------------------------------------------------------------------
__global__ __launch_bounds__(NTC, 2)
void mega_kernel(const float* __restrict__ x, const int* __restrict__ eidx,
                 const float* __restrict__ eattr, const float* __restrict__ pos,
                 const float* __restrict__ W1, const float* __restrict__ root1,
                 const float* __restrict__ b1,
                 const unsigned* __restrict__ W32hi, const unsigned* __restrict__ W32lo,
                 const float* __restrict__ b2,
                 const unsigned* __restrict__ W64hi, const unsigned* __restrict__ W64lo,
                 const float* __restrict__ b3,
                 const float* __restrict__ fc1w, const float* __restrict__ fc1b,
                 const float* __restrict__ fc2w, const float* __restrict__ fc2b,
                 float* __restrict__ out) {
    extern __shared__ __align__(16) char sm[];
    const int g = blockIdx.x, tid = threadIdx.x;
    const uint32_t sm32 = smem_to_u32(sm);
    const int lane = tid & 31, wid5 = tid >> 5;

    unsigned short* off2 = (unsigned short*)(sm + SM_OFF2);
    int*            degS = (int*)(sm + SM_DEG);
    float*          hcur = (float*)(sm + SM_HCUR);
    float*          swt  = (float*)(sm + BK_SWT);
    int*            cnt  = (int*)(sm + BK_CNT);
    float*          sdk  = (float*)(sm + BK_SDK);
    unsigned short* skey = (unsigned short*)(sm + BK_KEY);
    unsigned char*  ssr  = (unsigned char*)(sm + BK_SSR);
    int*            part = (int*)(sm + BK_PART);
    float*          xs   = (float*)(sm + BK_XS);
    float*          W1s  = (float*)(sm + SM_C);
    float*          r1s  = (float*)(sm + SM_C + 3200);
    float*          b1s  = (float*)(sm + SM_C + 3328);

    // ---- init
    for (int t = tid; t < NKEY; t += NTC) { cnt[t] = 0; sdk[t] = 0.0f; }
    if (tid < P_N) { degS[tid] = 0; xs[tid] = x[g * P_N + tid]; }
    for (int t = tid; t < 5 * HQ; t += NTC) hcur[P_N * HQ + t] = 0.0f;
    for (int t = tid; t < KK_C * 32; t += NTC) W1s[t] = W1[t];
    if (tid < 32) { r1s[tid] = root1[tid]; b1s[tid] = b1[tid]; }
    __syncthreads();

    // ---- bucket: basis + records + counts + sdk (conv1 partial sums)
    for (int el = tid; el < EPG; el += NTC) {
        const int e  = g * EPG + el;
        const float u0 = eattr[2 * e], u1 = eattr[2 * e + 1];
        const int src = eidx[e]       - g * P_N;
        const int dst = eidx[E_N + e] - g * P_N;
        atomicAdd(&degS[dst], 1);
        float p0 = u0 * (KS_C - 1), p1 = u1 * (KS_C - 1);
        float l0 = fminf(fmaxf(floorf(p0), 0.0f), (float)(KS_C - 1));
        float l1 = fminf(fmaxf(floorf(p1), 0.0f), (float)(KS_C - 1));
        float f0 = p0 - l0, f1 = p1 - l1;
        int i00 = (int)l0, i01 = min(i00 + 1, KS_C - 1);
        int i10 = (int)l1, i11 = min(i10 + 1, KS_C - 1);
        const float wa[2] = {1.0f - f0, f0};  const int ia[2] = {i00, i01};
        const float wb[2] = {1.0f - f1, f1};  const int ib[2] = {i10, i11};
        const float xv = xs[src];
        #pragma unroll
        for (int a = 0; a < 2; a++)
            #pragma unroll
            for (int b = 0; b < 2; b++) {
                const int slot = el * 4 + a * 2 + b;
                const int k = ia[a] + KS_C * ib[b];
                const int key = k * P_N + dst;
                skey[slot] = (unsigned short)key;
                ssr [slot] = (unsigned char)src;
                const float wv = wa[a] * wb[b];
                swt [slot] = wv;
                atomicAdd(&cnt[key], 1);
                atomicAdd(&sdk[key], wv * xv);
            }
    }
    __syncthreads();

    // ---- scan: warp-shuffle two-level (235 8-bucket blocks)
    int sum8 = 0;
    if (tid < 235) {
        #pragma unroll
        for (int j = 0; j < 8; j++) {
            int idx = tid * 8 + j;
            if (idx < NKEY) sum8 += cnt[idx];
        }
    }
    int v = sum8;
    #pragma unroll
    for (int o = 1; o < 32; o <<= 1) {
        int t = __shfl_up_sync(0xFFFFFFFFu, v, o);
        if (lane >= o) v += t;
    }
    if (lane == 31) part[wid5] = v;
    __syncthreads();
    if (tid == 0) {
        int run = 0;
        #pragma unroll
        for (int i = 0; i < 10; i++) { int t = part[i]; part[i] = run; run += t; }
    }
    __syncthreads();
    if (tid < 235) {
        int base = (v - sum8) + part[wid5];
        #pragma unroll
        for (int j = 0; j < 8; j++) {
            int idx = tid * 8 + j;
            if (idx < NKEY) { int c2 = cnt[idx]; cnt[idx] = base; base += c2; }
        }
    }
    __syncthreads();
    for (int t = tid; t < NKEY; t += NTC) off2[t] = (unsigned short)cnt[t];
    if (tid == 0) off2[NKEY] = (unsigned short)RPG;
    __syncthreads();

    // ---- scatter records (uint2) to gmem + conv1 from sdk
    uint2* grm = d_rec + g * RPG;
    for (int slot = tid; slot < RPG; slot += NTC) {
        const int key = skey[slot];
        const int p = atomicAdd(&cnt[key], 1);
        grm[p] = make_uint2(__float_as_uint(swt[slot]), (unsigned)ssr[slot]);
    }
    for (int it = tid; it < P_N * 32; it += NTC) {
        const int d = it >> 5, o = it & 31;
        float acc = 0.0f;
        #pragma unroll
        for (int k = 0; k < KK_C; k++) acc += sdk[k * P_N + d] * W1s[k * 32 + o];
        const float inv = 1.0f / (float)max(degS[d], 1);
        hcur[d * HQ + o] = elu_f(acc * inv + xs[d] * r1s[o] + b1s[o]);
    }

    // ---- conv layers
    conv_phase<32>(sm, sm32, W32hi, W32lo, b2, grm, tid);
    conv_phase<64>(sm, sm32, W64hi, W64lo, b3, grm, tid);

    // ---- head
    int*   vox = (int*)(sm + SM_C);
    float* gx  = (float*)(sm + SM_C + 304);
    float* f1  = (float*)(sm + SM_C + 1328);
    float* lg  = (float*)(sm + SM_C + 1840);

    if (tid < P_N) {
        const float p0 = pos[(g * P_N + tid) * 2 + 0];
        const float p1 = pos[(g * P_N + tid) * 2 + 1];
        const int v0 = min(max((int)(p0 / 14.0f), 0), 1);
        const int v1 = min(max((int)(p1 / 14.0f), 0), 1);
        vox[tid] = v0 + 2 * v1;
    }
    __syncthreads();
    if (tid < 256) {
        const int v2 = tid >> 6, c = tid & 63;
        float m = -3.402823466e38f; bool found = false;
        for (int r = 0; r < P_N; r++)
            if (vox[r] == v2) { m = fmaxf(m, hcur[r * HQ + c]); found = true; }
        gx[v2 * 64 + c] = found ? m : 0.0f;
    }
    __syncthreads();
    if (tid < 128) {
        float a = fc1b[tid];
        #pragma unroll 8
        for (int i = 0; i < 256; i++) a = fmaf(gx[i], fc1w[i * 128 + tid], a);
        f1[tid] = elu_f(a);
    }
    __syncthreads();
    if (tid < 10) {
        float a = fc2b[tid];
        #pragma unroll 8
        for (int i = 0; i < 128; i++) a = fmaf(f1[i], fc2w[i * 10 + tid], a);
        lg[tid] = a;
    }
    __syncthreads();
    if (tid == 0) {
        float m = lg[0];
        for (int o = 1; o < 10; o++) m = fmaxf(m, lg[o]);
        float s = 0.0f;
        for (int o = 0; o < 10; o++) s += expf(lg[o] - m);
        const float lse = m + logf(s);
        for (int o = 0; o < 10; o++) out[g * 10 + o] = lg[o] - lse;
    }
}

// ---------------------------------------------------------------------------
// Launch
// ---------------------------------------------------------------------------
extern "C" void kernel_launch(void* const* d_in, const int* in_sizes, int n_in,
                              void* d_out, int out_size) {
    const float* x     = (const float*)d_in[0];
    const int*   eidx  = (const int*)  d_in[1];
    const float* eattr = (const float*)d_in[2];
    const float* pos   = (const float*)d_in[4];
    const float* W1    = (const float*)d_in[5];
    const float* root1 = (const float*)d_in[6];
    const float* b1    = (const float*)d_in[7];
    const float* W2    = (const float*)d_in[8];
    const float* root2 = (const float*)d_in[9];
    const float* b2    = (const float*)d_in[10];
    const float* W3    = (const float*)d_in[11];
    const float* root3 = (const float*)d_in[12];
    const float* b3    = (const float*)d_in[13];
    const float* fc1w  = (const float*)d_in[14];
    const float* fc1b  = (const float*)d_in[15];
    const float* fc2w  = (const float*)d_in[16];
    const float* fc2b  = (const float*)d_in[17];
    float* out = (float*)d_out;

    void *w32h = nullptr, *w32l = nullptr, *w64h = nullptr, *w64l = nullptr;
    cudaGetSymbolAddress(&w32h, d_W32hi);
    cudaGetSymbolAddress(&w32l, d_W32lo);
    cudaGetSymbolAddress(&w64h, d_W64hi);
    cudaGetSymbolAddress(&w64l, d_W64lo);

    cudaFuncSetAttribute(mega_kernel, cudaFuncAttributeMaxDynamicSharedMemorySize, SM_TOTAL);

    prep_kernel<<<26, 256>>>(W2, root2, (unsigned*)w32h, (unsigned*)w32l, 32, WP32);
    prep_kernel<<<26, 256>>>(W3, root3, (unsigned*)w64h, (unsigned*)w64l, 64, WP64);
    mega_kernel<<<G_NUM, NTC, SM_TOTAL>>>(
        x, eidx, eattr, pos, W1, root1, b1,
        (const unsigned*)w32h, (const unsigned*)w32l, b2,
        (const unsigned*)w64h, (const unsigned*)w64l, b3,
        fc1w, fc1b, fc2w, fc2b, out);
}